// round 14
// baseline (speedup 1.0000x reference)
#include <cuda_runtime.h>
#include <cuda_bf16.h>
#include <math.h>
#include <stdint.h>

#define B_SZ 512
#define NV_EN 30000
#define NV_CN 20000
#define KT 100
#define HD 512
#define DE 300
#define TAU_ 1.0f
#define EPS_SK 0.1f

#define KP_EN 30016
#define KP_CN 20032
#define GR_EN 30080
#define GR_CN 20096

typedef __nv_bfloat16 bf16;

// ---------------- device scratch ----------------
__device__ __align__(16) bf16 g_Ahi[B_SZ * KP_EN];
__device__ __align__(16) bf16 g_Alo[B_SZ * KP_EN];
__device__ __align__(16) bf16 g_Bhi[B_SZ * KP_EN];
__device__ __align__(16) bf16 g_Blo[B_SZ * KP_EN];
__device__ __align__(16) bf16 g_A2hi[B_SZ * KP_CN];
__device__ __align__(16) bf16 g_A2lo[B_SZ * KP_CN];
__device__ __align__(16) bf16 g_B2hi[B_SZ * KP_CN];
__device__ __align__(16) bf16 g_B2lo[B_SZ * KP_CN];
__device__ __align__(16) bf16 g_W2Ehi[512 * 512];
__device__ __align__(16) bf16 g_W2Elo[512 * 512];
__device__ __align__(16) bf16 g_MVEhi[256 * 512];
__device__ __align__(16) bf16 g_MVElo[256 * 512];
__device__ __align__(16) bf16 g_W2Chi[512 * 512];
__device__ __align__(16) bf16 g_W2Clo[512 * 512];
__device__ __align__(16) bf16 g_MVChi[256 * 512];
__device__ __align__(16) bf16 g_MVClo[256 * 512];
__device__ __align__(16) bf16 g_WEhi[GR_EN * 320];
__device__ __align__(16) bf16 g_WElo[GR_EN * 320];
__device__ __align__(16) bf16 g_Thi [128 * 320];
__device__ __align__(16) bf16 g_Tlo [128 * 320];
__device__ __align__(16) bf16 g_BEhi[GR_EN * 128];
__device__ __align__(16) bf16 g_BElo[GR_EN * 128];
__device__ __align__(16) bf16 g_thEhi[B_SZ * 128];
__device__ __align__(16) bf16 g_thElo[B_SZ * 128];
__device__ __align__(16) bf16 g_WChi[GR_CN * 320];
__device__ __align__(16) bf16 g_WClo[GR_CN * 320];
__device__ __align__(16) bf16 g_T2hi[128 * 320];
__device__ __align__(16) bf16 g_T2lo[128 * 320];
__device__ __align__(16) bf16 g_BChi[GR_CN * 128];
__device__ __align__(16) bf16 g_BClo[GR_CN * 128];
__device__ __align__(16) bf16 g_thChi[B_SZ * 128];
__device__ __align__(16) bf16 g_thClo[B_SZ * 128];
__device__ __align__(16) float g_h1 [B_SZ * HD];
__device__ __align__(16) float g_h2 [B_SZ * HD];
__device__ __align__(16) float g_mulv [B_SZ * 200];
__device__ __align__(16) float g_h1c[B_SZ * HD];
__device__ __align__(16) float g_h2c[B_SZ * HD];
__device__ __align__(16) float g_mulvc[B_SZ * 200];
__device__ __align__(16) float g_G  [NV_EN * KT];
__device__ __align__(16) float g_G2 [NV_CN * KT];
__device__ __align__(16) float g_recon [B_SZ * NV_EN];
__device__ __align__(16) float g_recon2[B_SZ * NV_CN];
__device__ __align__(16) float g_theta_en[B_SZ * KT];
__device__ __align__(16) float g_theta_cn[B_SZ * KT];
__device__ __align__(16) float g_wnorm [NV_EN];
__device__ __align__(16) float g_wnorm2[NV_CN];
__device__ __align__(16) float g_tnorm [KT];
__device__ __align__(16) float g_tnorm2[KT];
__device__ __align__(16) float g_tn[B_SZ * KT];
__device__ __align__(16) float g_tnT[KT * DE];
__device__ __align__(16) float g_C[KT * KT];
__device__ __align__(16) float g_cs [KT];
__device__ __align__(16) float g_cs2[KT];
__device__ __align__(16) float g_acc[8];

// ======== pipelined split-bf16 mma.sync GEMM ========
#define KC 32
#define AST 40

__device__ __forceinline__ void split2(float x, bf16& h, bf16& l) {
    h = __float2bfloat16(x);
    l = __float2bfloat16(x - __bfloat162float(h));
}

__device__ __forceinline__ void mma16816(float* c, const uint32_t* a, uint32_t b0, uint32_t b1) {
    asm volatile(
        "mma.sync.aligned.m16n8k16.row.col.f32.bf16.bf16.f32 "
        "{%0,%1,%2,%3}, {%4,%5,%6,%7}, {%8,%9}, {%0,%1,%2,%3};"
        : "+f"(c[0]), "+f"(c[1]), "+f"(c[2]), "+f"(c[3])
        : "r"(a[0]), "r"(a[1]), "r"(a[2]), "r"(a[3]), "r"(b0), "r"(b1));
}

template<int SPLIT>
__global__ __launch_bounds__(256)
void tc_gemm3(const bf16* __restrict__ Ahi, const bf16* __restrict__ Alo,
              const bf16* __restrict__ Bhi, const bf16* __restrict__ Blo,
              float* __restrict__ C, int M, int N, int Kp,
              int chunksPerZ, int mode)
{
    extern __shared__ __align__(16) bf16 smem[];
    const int TILE = 128 * AST;
    const int NT = SPLIT ? 4 : 2;
    const int STAGE = NT * TILE;

    int tid = threadIdx.x;
    int warp = tid >> 5, lane = tid & 31;
    int wm = warp >> 1, wn = warp & 1;
    int row0 = blockIdx.y * 128;
    int col0 = blockIdx.x * 128;
    int totalChunks = Kp / KC;
    int c0 = blockIdx.z * chunksPerZ;
    int nC = min(chunksPerZ, totalChunks - c0);
    if (nC <= 0) return;

    float acc[2][8][4];
#pragma unroll
    for (int i = 0; i < 2; i++)
#pragma unroll
        for (int j = 0; j < 8; j++)
#pragma unroll
            for (int q = 0; q < 4; q++) acc[i][j][q] = 0.f;

    int g = lane >> 2, t4 = lane & 3;

    auto issue_copy = [&](int s, int k0) {
#pragma unroll
        for (int it = 0; it < 2 * NT; it++) {
            const int t = it >> 1;
            int idx = ((it & 1) << 8) | tid;
            int r = idx >> 2, j = idx & 3;
            const bf16* src;
            int rb;
            if (SPLIT) {
                src = (t == 0) ? Ahi : (t == 1) ? Alo : (t == 2) ? Bhi : Blo;
                rb = (t < 2) ? row0 : col0;
            } else {
                src = (t == 0) ? Ahi : Bhi;
                rb = (t == 0) ? row0 : col0;
            }
            const bf16* gp = src + (size_t)(rb + r) * Kp + k0 + j * 8;
            bf16* dp = smem + s * STAGE + t * TILE + r * AST + j * 8;
            uint32_t da = (uint32_t)__cvta_generic_to_shared(dp);
            asm volatile("cp.async.cg.shared.global [%0], [%1], 16;" :: "r"(da), "l"(gp));
        }
        asm volatile("cp.async.commit_group;" ::: "memory");
    };

    issue_copy(0, c0 * KC);

    for (int lc = 0; lc < nC; lc++) {
        if (lc + 1 < nC) {
            issue_copy((lc + 1) & 1, (c0 + lc + 1) * KC);
            asm volatile("cp.async.wait_group 1;" ::: "memory");
        } else {
            asm volatile("cp.async.wait_group 0;" ::: "memory");
        }
        __syncthreads();

        const bf16* sAh = smem + (lc & 1) * STAGE;
        const bf16* sAl = sAh + TILE;
        const bf16* sBh = SPLIT ? (sAh + 2 * TILE) : (sAh + TILE);
        const bf16* sBl = sAh + 3 * TILE;

#pragma unroll
        for (int ks = 0; ks < 2; ks++) {
            int kb = ks * 16 + t4 * 2;
            uint32_t ah[2][4], al[2][4];
#pragma unroll
            for (int mf = 0; mf < 2; mf++) {
                int ar = wm * 32 + mf * 16 + g;
                int base = ar * AST + kb;
                ah[mf][0] = *reinterpret_cast<const uint32_t*>(&sAh[base]);
                ah[mf][1] = *reinterpret_cast<const uint32_t*>(&sAh[base + 8 * AST]);
                ah[mf][2] = *reinterpret_cast<const uint32_t*>(&sAh[base + 8]);
                ah[mf][3] = *reinterpret_cast<const uint32_t*>(&sAh[base + 8 * AST + 8]);
                if (SPLIT) {
                    al[mf][0] = *reinterpret_cast<const uint32_t*>(&sAl[base]);
                    al[mf][1] = *reinterpret_cast<const uint32_t*>(&sAl[base + 8 * AST]);
                    al[mf][2] = *reinterpret_cast<const uint32_t*>(&sAl[base + 8]);
                    al[mf][3] = *reinterpret_cast<const uint32_t*>(&sAl[base + 8 * AST + 8]);
                }
            }
#pragma unroll
            for (int nf = 0; nf < 8; nf++) {
                int bn = wn * 64 + nf * 8 + g;
                int bbase = bn * AST + kb;
                uint32_t bh0 = *reinterpret_cast<const uint32_t*>(&sBh[bbase]);
                uint32_t bh1 = *reinterpret_cast<const uint32_t*>(&sBh[bbase + 8]);
#pragma unroll
                for (int mf = 0; mf < 2; mf++)
                    mma16816(acc[mf][nf], ah[mf], bh0, bh1);
                if (SPLIT) {
                    uint32_t bl0 = *reinterpret_cast<const uint32_t*>(&sBl[bbase]);
                    uint32_t bl1 = *reinterpret_cast<const uint32_t*>(&sBl[bbase + 8]);
#pragma unroll
                    for (int mf = 0; mf < 2; mf++) {
                        mma16816(acc[mf][nf], ah[mf], bl0, bl1);
                        mma16816(acc[mf][nf], al[mf], bh0, bh1);
                    }
                }
            }
        }
        __syncthreads();
    }

#pragma unroll
    for (int mf = 0; mf < 2; mf++) {
#pragma unroll
        for (int nf = 0; nf < 8; nf++) {
            int r = row0 + wm * 32 + mf * 16 + g;
            int c = col0 + wn * 64 + nf * 8 + t4 * 2;
            float* a4 = acc[mf][nf];
#pragma unroll
            for (int h = 0; h < 2; h++) {
                int rr = r + h * 8;
                if (rr >= M) continue;
#pragma unroll
                for (int q = 0; q < 2; q++) {
                    int cc = c + q;
                    if (cc >= N) continue;
                    float v = a4[h * 2 + q];
                    if (mode) atomicAdd(&C[(size_t)rr * N + cc], v);
                    else C[(size_t)rr * N + cc] = v;
                }
            }
        }
    }
}

// ---------------- conversions ----------------
__global__ void conv_pad(const float* __restrict__ src, bf16* __restrict__ hi, bf16* __restrict__ lo,
                         int R, int K, int Kp) {
    size_t total = (size_t)R * Kp;
    for (size_t idx = blockIdx.x * (size_t)blockDim.x + threadIdx.x; idx < total;
         idx += (size_t)gridDim.x * blockDim.x) {
        int r = (int)(idx / Kp), k = (int)(idx % Kp);
        float v = (k < K) ? src[(size_t)r * K + k] : 0.f;
        bf16 h, l; split2(v, h, l);
        hi[idx] = h; lo[idx] = l;
    }
}

__global__ void tconv(const float* __restrict__ src, bf16* __restrict__ hi, bf16* __restrict__ lo,
                      int R, int C, int Kp) {
    __shared__ float t[32][33];
    int kb = blockIdx.y * 32, nb = blockIdx.x * 32;
    int tx = threadIdx.x, ty = threadIdx.y;
#pragma unroll
    for (int i = 0; i < 4; i++) {
        int r = kb + ty + i * 8, c = nb + tx;
        t[ty + i * 8][tx] = (r < R && c < C) ? src[(size_t)r * C + c] : 0.f;
    }
    __syncthreads();
#pragma unroll
    for (int i = 0; i < 4; i++) {
        int n = nb + ty + i * 8, k = kb + tx;
        if (n < C && k < Kp) {
            bf16 h, l; split2(t[tx][ty + i * 8], h, l);
            hi[(size_t)n * Kp + k] = h;
            lo[(size_t)n * Kp + k] = l;
        }
    }
}

__global__ void bias_sp_conv(const float* __restrict__ X, const float* __restrict__ bias,
                             bf16* __restrict__ hi, bf16* __restrict__ lo, int M, int N) {
    int total = M * N;
    for (int idx = blockIdx.x * blockDim.x + threadIdx.x; idx < total; idx += gridDim.x * blockDim.x) {
        int j = idx % N;
        float v = X[idx] + bias[j];
        float sp = fmaxf(v, 0.f) + log1pf(expf(-fabsf(v)));
        bf16 h, l; split2(sp, h, l);
        hi[idx] = h; lo[idx] = l;
    }
}

// ---------------- elementwise / reductions ----------------
__global__ void zero_kernel(float* p, int n) {
    for (int i = blockIdx.x * blockDim.x + threadIdx.x; i < n; i += gridDim.x * blockDim.x)
        p[i] = 0.f;
}

__global__ void theta_kl_kernel(const float* __restrict__ mulv,
                                const float* __restrict__ bmu, const float* __restrict__ blv,
                                const float* __restrict__ eps, float* __restrict__ theta_scratch,
                                float* __restrict__ theta_dout,
                                bf16* __restrict__ thi, bf16* __restrict__ tlo, float* kl_acc)
{
    int i = blockIdx.x;
    int k = threadIdx.x;
    __shared__ float red[128];
    float zv = -1e30f, kl = 0.f;
    if (k < KT) {
        float mu = mulv[i * 200 + k] + bmu[k];
        float lv = mulv[i * 200 + 100 + k] + blv[k];
        zv = mu + eps[i * KT + k] * expf(0.5f * lv);
        kl = expf(lv) + mu * mu - 1.f - lv;
    }
    red[k] = zv; __syncthreads();
    for (int s = 64; s > 0; s >>= 1) { if (k < s) red[k] = fmaxf(red[k], red[k + s]); __syncthreads(); }
    float m = red[0]; __syncthreads();
    float e = (k < KT) ? expf(zv - m) : 0.f;
    red[k] = e; __syncthreads();
    for (int s = 64; s > 0; s >>= 1) { if (k < s) red[k] += red[k + s]; __syncthreads(); }
    float ssum = red[0]; __syncthreads();
    {
        float t = (k < KT) ? (e / ssum) : 0.f;
        if (k < KT) {
            theta_scratch[i * KT + k] = t;
            theta_dout[i * KT + k] = t;
        }
        bf16 h, l; split2(t, h, l);
        thi[i * 128 + k] = h;
        tlo[i * 128 + k] = l;
    }
    red[k] = (k < KT) ? kl : 0.f; __syncthreads();
    for (int s = 64; s > 0; s >>= 1) { if (k < s) red[k] += red[k + s]; __syncthreads(); }
    if (k == 0) atomicAdd(kl_acc, 0.5f * red[0]);
}

__global__ void rownorm2_kernel(const float* __restrict__ X, float* __restrict__ out, int R, int D) {
    int warp = (blockIdx.x * blockDim.x + threadIdx.x) >> 5;
    int lane = threadIdx.x & 31;
    if (warp >= R) return;
    float s = 0.f;
    for (int d = lane; d < D; d += 32) { float v = X[(size_t)warp * D + d]; s = fmaf(v, v, s); }
    for (int o = 16; o; o >>= 1) s += __shfl_down_sync(0xffffffffu, s, o);
    if (lane == 0) out[warp] = s;
}

__global__ void beta_pass1(const float* __restrict__ G, const float* __restrict__ wnorm,
                           const float* __restrict__ tnorm, float* __restrict__ beta_dout,
                           float* __restrict__ colsum, int V)
{
    __shared__ float tn_s[KT];
    __shared__ float wsum[8];
    int v = blockIdx.x * 256 + threadIdx.x;
    if (threadIdx.x < KT) tn_s[threadIdx.x] = tnorm[threadIdx.x];
    __syncthreads();
    bool ok = v < V;
    float wn = ok ? wnorm[v] : 0.f;
    int lane = threadIdx.x & 31, wid = threadIdx.x >> 5;
    for (int k = 0; k < KT; k++) {
        float e = 0.f;
        if (ok) {
            float sq = wn + tn_s[k] - 2.f * G[(size_t)v * KT + k];
            float d = sqrtf(fmaxf(sq, 0.f));
            e = expf(-d / TAU_);
            beta_dout[(size_t)k * V + v] = e;
        }
        float s = e;
        for (int o = 16; o; o >>= 1) s += __shfl_down_sync(0xffffffffu, s, o);
        if (lane == 0) wsum[wid] = s;
        __syncthreads();
        if (threadIdx.x == 0) {
            float t = 0.f;
            for (int w = 0; w < 8; w++) t += wsum[w];
            atomicAdd(&colsum[k], t);
        }
        __syncthreads();
    }
}

__global__ void beta_pass2(float* __restrict__ beta_dout, const float* __restrict__ colsum, int V) {
    int total = KT * V;
    for (int idx = blockIdx.x * blockDim.x + threadIdx.x; idx < total; idx += gridDim.x * blockDim.x) {
        int k = idx / V;
        beta_dout[idx] = beta_dout[idx] / colsum[k];
    }
}

__global__ void recon_loss_kernel(const float* __restrict__ x, const float* __restrict__ recon,
                                  int V, float* acc)
{
    int i = blockIdx.x;
    int tid = threadIdx.x;
    float m = -1e30f, s = 0.f, dot = 0.f, sx = 0.f;
    for (int v = tid; v < V; v += 256) {
        float r = recon[(size_t)i * V + v];
        float xv = x[(size_t)i * V + v];
        if (r > m) { s = s * expf(m - r) + 1.f; m = r; }
        else s += expf(r - m);
        dot = fmaf(xv, r, dot);
        sx += xv;
    }
    __shared__ float sm[256], ss[256], sd[256], sxs[256];
    sm[tid] = m; ss[tid] = s; sd[tid] = dot; sxs[tid] = sx;
    __syncthreads();
    for (int o = 128; o; o >>= 1) {
        if (tid < o) {
            float m1 = sm[tid], s1 = ss[tid];
            float m2 = sm[tid + o], s2 = ss[tid + o];
            float M_ = fmaxf(m1, m2);
            sm[tid] = M_;
            ss[tid] = s1 * expf(m1 - M_) + s2 * expf(m2 - M_);
            sd[tid] += sd[tid + o];
            sxs[tid] += sxs[tid + o];
        }
        __syncthreads();
    }
    if (tid == 0) {
        float lse = sm[0] + logf(ss[0]);
        atomicAdd(acc, -sd[0] + sxs[0] * lse);
    }
}

__global__ void select_norm_kernel(const float* __restrict__ theta_en,
                                   const float* __restrict__ theta_cn, float* __restrict__ tn)
{
    int i = blockIdx.x;
    int k = threadIdx.x;
    __shared__ float red[128];
    const float* src = ((i & 1) == 0) ? theta_en : theta_cn;
    float v = (k < KT) ? src[i * KT + k] : 0.f;
    red[k] = v * v; __syncthreads();
    for (int s = 64; s > 0; s >>= 1) { if (k < s) red[k] += red[k + s]; __syncthreads(); }
    float nrm = fmaxf(sqrtf(red[0]), 1e-8f);
    if (k < KT) tn[i * KT + k] = v / nrm;
}

__global__ void contrast_kernel(const float* __restrict__ tn, const int* __restrict__ cid, float* acc)
{
    int i = blockIdx.x;
    int tid = threadIdx.x;
    __shared__ float ti[KT];
    if (tid < KT) ti[tid] = tn[i * KT + tid];
    __syncthreads();
    int ci = cid[i];
    bool vi = ci > 0;
    float pos = 0.f, neg = 0.f, pcnt = 0.f;
    for (int j = tid; j < B_SZ; j += 256) {
        if (j == i) continue;
        float s = 0.f;
        const float* tj = &tn[j * KT];
#pragma unroll 4
        for (int k = 0; k < KT; k++) s = fmaf(ti[k], tj[k], s);
        float E = expf(s / TAU_);
        neg += E;
        int cj = cid[j];
        if (vi && cj > 0 && cj == ci) { pos += E; pcnt += 1.f; }
    }
    __shared__ float r1[256], r2[256], r3[256];
    r1[tid] = pos; r2[tid] = neg; r3[tid] = pcnt;
    __syncthreads();
    for (int o = 128; o; o >>= 1) {
        if (tid < o) { r1[tid] += r1[tid + o]; r2[tid] += r2[tid + o]; r3[tid] += r3[tid + o]; }
        __syncthreads();
    }
    if (tid == 0) {
        if (vi && r3[0] > 0.5f) {
            float per = -logf(r1[0] / (r1[0] + r2[0] + 1e-8f));
            atomicAdd(&acc[4], per);
            atomicAdd(&acc[5], 1.f);
        }
    }
}

__global__ void norm_topic_kernel(const float* __restrict__ T, float* __restrict__ Tn) {
    int k = blockIdx.x;
    int d = threadIdx.x;
    __shared__ float red[128];
    float s = 0.f;
    for (int dd = d; dd < DE; dd += 128) { float v = T[k * DE + dd]; s = fmaf(v, v, s); }
    red[d] = s; __syncthreads();
    for (int o = 64; o > 0; o >>= 1) { if (d < o) red[d] += red[d + o]; __syncthreads(); }
    float nrm = fmaxf(sqrtf(red[0]), 1e-8f);
    for (int dd = d; dd < DE; dd += 128) Tn[k * DE + dd] = T[k * DE + dd] / nrm;
}

__global__ void cmat_kernel(const float* __restrict__ Tn, float* __restrict__ C) {
    int i = blockIdx.x;
    __shared__ float ti[DE];
    for (int d = threadIdx.x; d < DE; d += 128) ti[d] = Tn[i * DE + d];
    __syncthreads();
    for (int j = threadIdx.x; j < KT; j += 128) {
        float s = 0.f;
        for (int d = 0; d < DE; d++) s = fmaf(ti[d], Tn[j * DE + d], s);
        C[i * KT + j] = 1.f - s;
    }
}

__global__ void sinkhorn_kernel(const float* __restrict__ C, float* acc) {
    __shared__ float Ks[KT * KT];
    __shared__ float u[KT], v[KT];
    __shared__ float red[256];
    int tid = threadIdx.x;
    for (int idx = tid; idx < KT * KT; idx += 256) Ks[idx] = expf(-C[idx] / EPS_SK);
    if (tid < KT) { u[tid] = 1.f; v[tid] = 1.f; }
    __syncthreads();
    const float a = 1.f / KT;
    for (int it = 0; it < 50; it++) {
        if (tid < KT) {
            float d = 1e-8f;
            for (int j = 0; j < KT; j++) d = fmaf(Ks[tid * KT + j], v[j], d);
            u[tid] = a / d;
        }
        __syncthreads();
        if (tid < KT) {
            float d = 1e-8f;
            for (int i2 = 0; i2 < KT; i2++) d = fmaf(Ks[i2 * KT + tid], u[i2], d);
            v[tid] = a / d;
        }
        __syncthreads();
    }
    float s = 0.f;
    for (int idx = tid; idx < KT * KT; idx += 256) {
        int i2 = idx / KT, j = idx % KT;
        s += u[i2] * Ks[idx] * v[j] * C[idx];
    }
    red[tid] = s; __syncthreads();
    for (int o = 128; o; o >>= 1) { if (tid < o) red[tid] += red[tid + o]; __syncthreads(); }
    if (tid == 0) acc[6] = red[0];
}

__global__ void finalize_kernel(const float* __restrict__ acc, float* __restrict__ out) {
    float tm_en = acc[0] / (float)B_SZ + acc[1] / (float)B_SZ;
    float tm_cn = acc[2] / (float)B_SZ + acc[3] / (float)B_SZ;
    float contrast = acc[4] / (acc[5] + 1e-8f);
    float align = acc[6];
    out[0] = tm_en + tm_cn + contrast + align;
    out[1] = tm_en;
    out[2] = tm_cn;
    out[3] = contrast;
    out[4] = align;
}

// ---------------- host ----------------
template<int SPLIT>
static inline void launch_tc3(const bf16* Ah, const bf16* Al, const bf16* Bh, const bf16* Bl,
                              float* C, int M, int N, int Kp, int z, int mode, cudaStream_t st)
{
    size_t sm = (size_t)(SPLIT ? 4 : 2) * 2 * 128 * AST * sizeof(bf16);
    cudaFuncSetAttribute(tc_gemm3<SPLIT>, cudaFuncAttributeMaxDynamicSharedMemorySize, 98304);
    int total = Kp / KC;
    int per = (total + z - 1) / z;
    dim3 g((N + 127) / 128, (M + 127) / 128, z);
    tc_gemm3<SPLIT><<<g, 256, sm, st>>>(Ah, Al, Bh, Bl, C, M, N, Kp, per, mode);
}

extern "C" void kernel_launch(void* const* d_in, const int* in_sizes, int n_in,
                              void* d_out, int out_size)
{
    const float* x_en   = (const float*)d_in[0];
    const float* x_cn   = (const float*)d_in[1];
    const int*   cid    = (const int*)  d_in[2];
    const float* eps_en = (const float*)d_in[3];
    const float* eps_cn = (const float*)d_in[4];
    const float* W1_en  = (const float*)d_in[5];
    const float* b1_en  = (const float*)d_in[6];
    const float* W2_en  = (const float*)d_in[7];
    const float* b2_en  = (const float*)d_in[8];
    const float* Wmu_en = (const float*)d_in[9];
    const float* bmu_en = (const float*)d_in[10];
    const float* Wlv_en = (const float*)d_in[11];
    const float* blv_en = (const float*)d_in[12];
    const float* W1_cn  = (const float*)d_in[13];
    const float* b1_cn  = (const float*)d_in[14];
    const float* W2_cn  = (const float*)d_in[15];
    const float* b2_cn  = (const float*)d_in[16];
    const float* Wmu_cn = (const float*)d_in[17];
    const float* bmu_cn = (const float*)d_in[18];
    const float* Wlv_cn = (const float*)d_in[19];
    const float* blv_cn = (const float*)d_in[20];
    const float* we_en  = (const float*)d_in[21];
    const float* we_cn  = (const float*)d_in[22];
    const float* topic  = (const float*)d_in[23];

    float* out = (float*)d_out;
    float* theta_en_out = out + 5;
    float* theta_cn_out = theta_en_out + B_SZ * KT;
    float* beta_en_out  = theta_cn_out + B_SZ * KT;
    float* beta_cn_out  = beta_en_out + KT * NV_EN;

    static cudaStream_t s1 = nullptr, s2 = nullptr, s3 = nullptr;
    static cudaEvent_t eF, eMt, e1t, e2e, e3e, eW1E, eWsmE, eW1C, eWsmC;
    if (!s1) {
        cudaStreamCreateWithFlags(&s1, cudaStreamNonBlocking);
        cudaStreamCreateWithFlags(&s2, cudaStreamNonBlocking);
        cudaStreamCreateWithFlags(&s3, cudaStreamNonBlocking);
        cudaEventCreateWithFlags(&eF,   cudaEventDisableTiming);
        cudaEventCreateWithFlags(&eMt,  cudaEventDisableTiming);
        cudaEventCreateWithFlags(&e1t,  cudaEventDisableTiming);
        cudaEventCreateWithFlags(&e2e,  cudaEventDisableTiming);
        cudaEventCreateWithFlags(&e3e,  cudaEventDisableTiming);
        cudaEventCreateWithFlags(&eW1E, cudaEventDisableTiming);
        cudaEventCreateWithFlags(&eWsmE, cudaEventDisableTiming);
        cudaEventCreateWithFlags(&eW1C, cudaEventDisableTiming);
        cudaEventCreateWithFlags(&eWsmC, cudaEventDisableTiming);
    }

    float *h1, *h2, *mulv, *h1c, *h2c, *mulvc, *G, *G2, *recon, *recon2,
          *th_en, *th_cn, *wn, *wn2, *tnm, *tnm2, *tnb, *tnT, *Cm, *cs, *cs2, *acc;
    bf16 *Ahi, *Alo, *Bhi, *Blo, *A2hi, *A2lo, *B2hi, *B2lo,
         *W2Ehi, *W2Elo, *MVEhi, *MVElo, *W2Chi, *W2Clo, *MVChi, *MVClo,
         *WEhi, *WElo, *Thi, *Tlo, *BEhi, *BElo, *thEhi, *thElo,
         *WChi, *WClo, *T2hi, *T2lo, *BChi, *BClo, *thChi, *thClo;
    cudaGetSymbolAddress((void**)&Ahi,   g_Ahi);   cudaGetSymbolAddress((void**)&Alo,   g_Alo);
    cudaGetSymbolAddress((void**)&Bhi,   g_Bhi);   cudaGetSymbolAddress((void**)&Blo,   g_Blo);
    cudaGetSymbolAddress((void**)&A2hi,  g_A2hi);  cudaGetSymbolAddress((void**)&A2lo,  g_A2lo);
    cudaGetSymbolAddress((void**)&B2hi,  g_B2hi);  cudaGetSymbolAddress((void**)&B2lo,  g_B2lo);
    cudaGetSymbolAddress((void**)&W2Ehi, g_W2Ehi); cudaGetSymbolAddress((void**)&W2Elo, g_W2Elo);
    cudaGetSymbolAddress((void**)&MVEhi, g_MVEhi); cudaGetSymbolAddress((void**)&MVElo, g_MVElo);
    cudaGetSymbolAddress((void**)&W2Chi, g_W2Chi); cudaGetSymbolAddress((void**)&W2Clo, g_W2Clo);
    cudaGetSymbolAddress((void**)&MVChi, g_MVChi); cudaGetSymbolAddress((void**)&MVClo, g_MVClo);
    cudaGetSymbolAddress((void**)&WEhi,  g_WEhi);  cudaGetSymbolAddress((void**)&WElo,  g_WElo);
    cudaGetSymbolAddress((void**)&Thi,   g_Thi);   cudaGetSymbolAddress((void**)&Tlo,   g_Tlo);
    cudaGetSymbolAddress((void**)&BEhi,  g_BEhi);  cudaGetSymbolAddress((void**)&BElo,  g_BElo);
    cudaGetSymbolAddress((void**)&thEhi, g_thEhi); cudaGetSymbolAddress((void**)&thElo, g_thElo);
    cudaGetSymbolAddress((void**)&WChi,  g_WChi);  cudaGetSymbolAddress((void**)&WClo,  g_WClo);
    cudaGetSymbolAddress((void**)&T2hi,  g_T2hi);  cudaGetSymbolAddress((void**)&T2lo,  g_T2lo);
    cudaGetSymbolAddress((void**)&BChi,  g_BChi);  cudaGetSymbolAddress((void**)&BClo,  g_BClo);
    cudaGetSymbolAddress((void**)&thChi, g_thChi); cudaGetSymbolAddress((void**)&thClo, g_thClo);
    cudaGetSymbolAddress((void**)&h1,    g_h1);    cudaGetSymbolAddress((void**)&h2,    g_h2);
    cudaGetSymbolAddress((void**)&mulv,  g_mulv);
    cudaGetSymbolAddress((void**)&h1c,   g_h1c);   cudaGetSymbolAddress((void**)&h2c,   g_h2c);
    cudaGetSymbolAddress((void**)&mulvc, g_mulvc);
    cudaGetSymbolAddress((void**)&G,     g_G);     cudaGetSymbolAddress((void**)&G2,    g_G2);
    cudaGetSymbolAddress((void**)&recon, g_recon); cudaGetSymbolAddress((void**)&recon2, g_recon2);
    cudaGetSymbolAddress((void**)&th_en, g_theta_en);
    cudaGetSymbolAddress((void**)&th_cn, g_theta_cn);
    cudaGetSymbolAddress((void**)&wn,    g_wnorm); cudaGetSymbolAddress((void**)&wn2,   g_wnorm2);
    cudaGetSymbolAddress((void**)&tnm,   g_tnorm); cudaGetSymbolAddress((void**)&tnm2,  g_tnorm2);
    cudaGetSymbolAddress((void**)&tnb,   g_tn);
    cudaGetSymbolAddress((void**)&tnT,   g_tnT);
    cudaGetSymbolAddress((void**)&Cm,    g_C);
    cudaGetSymbolAddress((void**)&cs,    g_cs);    cudaGetSymbolAddress((void**)&cs2,   g_cs2);
    cudaGetSymbolAddress((void**)&acc,   g_acc);

    dim3 tb(32, 8);

    // ---- fork ----  (launch #1)
    zero_kernel<<<1, 64>>>(acc, 8);
    cudaEventRecord(eF, 0);
    cudaStreamWaitEvent(s1, eF, 0);
    cudaStreamWaitEvent(s2, eF, 0);
    cudaStreamWaitEvent(s3, eF, 0);

    // launch #2: W1_en conversion on s2, then record its event
    tconv<<<dim3(16, 938), tb, 0, s2>>>(W1_en, Bhi, Blo, NV_EN, HD, KP_EN);
    cudaEventRecord(eW1E, s2);

    // launches #3-#5: stream-0 EN prologue; launch #6 = BIG EN GEMM (ncu -s 5 -c 1 target)
    zero_kernel<<<1024, 256>>>(h1, B_SZ * HD);
    zero_kernel<<<1024, 256>>>(h2, B_SZ * HD);
    conv_pad<<<4096, 256>>>(x_en, Ahi, Alo, B_SZ, NV_EN, KP_EN);
    cudaStreamWaitEvent(0, eW1E, 0);
    launch_tc3<1>(Ahi, Alo, Bhi, Blo, h1, B_SZ, HD, KP_EN, 16, 1, 0);

    // s2: rest of EN weight conversions
    tconv<<<dim3(16, 16), tb, 0, s2>>>(W2_en, W2Ehi, W2Elo, HD, HD, 512);
    tconv<<<dim3(4, 16), tb, 0, s2>>>(Wmu_en, MVEhi, MVElo, HD, KT, 512);
    tconv<<<dim3(4, 16), tb, 0, s2>>>(Wlv_en, MVEhi + 100 * 512, MVElo + 100 * 512, HD, KT, 512);
    cudaEventRecord(eWsmE, s2);

    // stream 0: rest of EN encoder
    zero_kernel<<<512, 256>>>(mulv, B_SZ * 200);
    bias_sp_conv<<<1024, 256>>>(h1, b1_en, Ahi, Alo, B_SZ, HD);
    cudaStreamWaitEvent(0, eWsmE, 0);
    launch_tc3<1>(Ahi, Alo, W2Ehi, W2Elo, h2, B_SZ, HD, 512, 8, 1, 0);
    bias_sp_conv<<<1024, 256>>>(h2, b2_en, Ahi, Alo, B_SZ, HD);
    launch_tc3<1>(Ahi, Alo, MVEhi, MVElo, mulv, B_SZ, 200, 512, 8, 1, 0);
    theta_kl_kernel<<<B_SZ, 128>>>(mulv, bmu_en, blv_en, eps_en, th_en, theta_en_out, thEhi, thElo, acc + 1);
    cudaEventRecord(eMt, 0);

    // ======== stream s3: CN weight conversions ========
    tconv<<<dim3(16, 626), tb, 0, s3>>>(W1_cn, B2hi, B2lo, NV_CN, HD, KP_CN);
    cudaEventRecord(eW1C, s3);
    tconv<<<dim3(16, 16), tb, 0, s3>>>(W2_cn, W2Chi, W2Clo, HD, HD, 512);
    tconv<<<dim3(4, 16), tb, 0, s3>>>(Wmu_cn, MVChi, MVClo, HD, KT, 512);
    tconv<<<dim3(4, 16), tb, 0, s3>>>(Wlv_cn, MVChi + 100 * 512, MVClo + 100 * 512, HD, KT, 512);
    cudaEventRecord(eWsmC, s3);

    // ======== stream s1: CN encoder ========
    zero_kernel<<<1024, 256, 0, s1>>>(h1c, B_SZ * HD);
    zero_kernel<<<1024, 256, 0, s1>>>(h2c, B_SZ * HD);
    zero_kernel<<<512, 256, 0, s1>>>(mulvc, B_SZ * 200);
    conv_pad<<<4096, 256, 0, s1>>>(x_cn, A2hi, A2lo, B_SZ, NV_CN, KP_CN);
    cudaStreamWaitEvent(s1, eW1C, 0);
    launch_tc3<1>(A2hi, A2lo, B2hi, B2lo, h1c, B_SZ, HD, KP_CN, 16, 1, s1);
    bias_sp_conv<<<1024, 256, 0, s1>>>(h1c, b1_cn, A2hi, A2lo, B_SZ, HD);
    cudaStreamWaitEvent(s1, eWsmC, 0);
    launch_tc3<1>(A2hi, A2lo, W2Chi, W2Clo, h2c, B_SZ, HD, 512, 8, 1, s1);
    bias_sp_conv<<<1024, 256, 0, s1>>>(h2c, b2_cn, A2hi, A2lo, B_SZ, HD);
    launch_tc3<1>(A2hi, A2lo, MVChi, MVClo, mulvc, B_SZ, 200, 512, 8, 1, s1);
    theta_kl_kernel<<<B_SZ, 128, 0, s1>>>(mulvc, bmu_cn, blv_cn, eps_cn, th_cn, theta_cn_out, thChi, thClo, acc + 3);
    cudaEventRecord(e1t, s1);

    // ======== stream s2: beta EN + recon EN ========
    rownorm2_kernel<<<(NV_EN * 32 + 255) / 256, 256, 0, s2>>>(we_en, wn, NV_EN, DE);
    rownorm2_kernel<<<(KT * 32 + 255) / 256, 256, 0, s2>>>(topic, tnm, KT, DE);
    conv_pad<<<256, 256, 0, s2>>>(topic, Thi, Tlo, KT, DE, 320);
    conv_pad<<<4096, 256, 0, s2>>>(we_en, WEhi, WElo, NV_EN, DE, 320);
    launch_tc3<1>(WEhi, WElo, Thi, Tlo, G, NV_EN, KT, 320, 1, 0, s2);
    zero_kernel<<<1, 128, 0, s2>>>(cs, KT);
    beta_pass1<<<(NV_EN + 255) / 256, 256, 0, s2>>>(G, wn, tnm, beta_en_out, cs, NV_EN);
    beta_pass2<<<2048, 256, 0, s2>>>(beta_en_out, cs, NV_EN);
    tconv<<<dim3(938, 4), tb, 0, s2>>>(beta_en_out, BEhi, BElo, KT, NV_EN, 128);
    cudaStreamWaitEvent(s2, eMt, 0);
    launch_tc3<0>(thEhi, thElo, BEhi, BElo, recon, B_SZ, NV_EN, 128, 1, 0, s2);
    recon_loss_kernel<<<B_SZ, 256, 0, s2>>>(x_en, recon, NV_EN, acc + 0);
    cudaEventRecord(e2e, s2);

    // ======== stream s3: beta CN + recon CN ========
    rownorm2_kernel<<<(NV_CN * 32 + 255) / 256, 256, 0, s3>>>(we_cn, wn2, NV_CN, DE);
    rownorm2_kernel<<<(KT * 32 + 255) / 256, 256, 0, s3>>>(topic, tnm2, KT, DE);
    conv_pad<<<256, 256, 0, s3>>>(topic, T2hi, T2lo, KT, DE, 320);
    conv_pad<<<4096, 256, 0, s3>>>(we_cn, WChi, WClo, NV_CN, DE, 320);
    launch_tc3<1>(WChi, WClo, T2hi, T2lo, G2, NV_CN, KT, 320, 1, 0, s3);
    zero_kernel<<<1, 128, 0, s3>>>(cs2, KT);
    beta_pass1<<<(NV_CN + 255) / 256, 256, 0, s3>>>(G2, wn2, tnm2, beta_cn_out, cs2, NV_CN);
    beta_pass2<<<2048, 256, 0, s3>>>(beta_cn_out, cs2, NV_CN);
    tconv<<<dim3(626, 4), tb, 0, s3>>>(beta_cn_out, BChi, BClo, KT, NV_CN, 128);
    cudaStreamWaitEvent(s3, e1t, 0);
    launch_tc3<0>(thChi, thClo, BChi, BClo, recon2, B_SZ, NV_CN, 128, 1, 0, s3);
    recon_loss_kernel<<<B_SZ, 256, 0, s3>>>(x_cn, recon2, NV_CN, acc + 2);
    cudaEventRecord(e3e, s3);

    // ======== stream 0: alignment, contrastive, join ========
    norm_topic_kernel<<<KT, 128>>>(topic, tnT);
    cmat_kernel<<<KT, 128>>>(tnT, Cm);
    sinkhorn_kernel<<<1, 256>>>(Cm, acc);
    cudaStreamWaitEvent(0, e1t, 0);
    select_norm_kernel<<<B_SZ, 128>>>(th_en, th_cn, tnb);
    contrast_kernel<<<B_SZ, 256>>>(tnb, cid, acc);
    cudaStreamWaitEvent(0, e2e, 0);
    cudaStreamWaitEvent(0, e3e, 0);
    finalize_kernel<<<1, 1>>>(acc, out);
}

// round 15
// speedup vs baseline: 1.1642x; 1.1642x over previous
#include <cuda_runtime.h>
#include <cuda_bf16.h>
#include <cuda_fp16.h>
#include <math.h>
#include <stdint.h>

#define B_SZ 512
#define NV_EN 30000
#define NV_CN 20000
#define KT 100
#define HD 512
#define DE 300
#define TAU_ 1.0f
#define EPS_SK 0.1f

#define KP_EN 30016
#define KP_CN 20032
#define GR_EN 30080
#define GR_CN 20096

typedef __nv_bfloat16 bf16;
typedef __half fp16;

// ---------------- device scratch ----------------
__device__ __align__(16) bf16 g_Ahi[B_SZ * KP_EN];     // also used as fp16 x_en
__device__ __align__(16) bf16 g_Bhi[B_SZ * KP_EN];     // also fp16 W1 hi
__device__ __align__(16) bf16 g_Blo[B_SZ * KP_EN];     // also fp16 W1 lo
__device__ __align__(16) bf16 g_Alo[B_SZ * HD];        // encoder h lo (small now)
__device__ __align__(16) bf16 g_Ahs[B_SZ * HD];        // encoder h hi
__device__ __align__(16) bf16 g_A2hi[B_SZ * KP_CN];
__device__ __align__(16) bf16 g_B2hi[B_SZ * KP_CN];
__device__ __align__(16) bf16 g_B2lo[B_SZ * KP_CN];
__device__ __align__(16) bf16 g_A2lo[B_SZ * HD];
__device__ __align__(16) bf16 g_A2hs[B_SZ * HD];
__device__ __align__(16) bf16 g_W2Ehi[512 * 512];
__device__ __align__(16) bf16 g_W2Elo[512 * 512];
__device__ __align__(16) bf16 g_MVEhi[256 * 512];
__device__ __align__(16) bf16 g_MVElo[256 * 512];
__device__ __align__(16) bf16 g_W2Chi[512 * 512];
__device__ __align__(16) bf16 g_W2Clo[512 * 512];
__device__ __align__(16) bf16 g_MVChi[256 * 512];
__device__ __align__(16) bf16 g_MVClo[256 * 512];
__device__ __align__(16) bf16 g_WEhi[GR_EN * 320];
__device__ __align__(16) bf16 g_WElo[GR_EN * 320];
__device__ __align__(16) bf16 g_Thi [128 * 320];
__device__ __align__(16) bf16 g_Tlo [128 * 320];
__device__ __align__(16) bf16 g_BEhi[GR_EN * 128];
__device__ __align__(16) bf16 g_BElo[GR_EN * 128];
__device__ __align__(16) bf16 g_thEhi[B_SZ * 128];
__device__ __align__(16) bf16 g_thElo[B_SZ * 128];
__device__ __align__(16) bf16 g_WChi[GR_CN * 320];
__device__ __align__(16) bf16 g_WClo[GR_CN * 320];
__device__ __align__(16) bf16 g_T2hi[128 * 320];
__device__ __align__(16) bf16 g_T2lo[128 * 320];
__device__ __align__(16) bf16 g_BChi[GR_CN * 128];
__device__ __align__(16) bf16 g_BClo[GR_CN * 128];
__device__ __align__(16) bf16 g_thChi[B_SZ * 128];
__device__ __align__(16) bf16 g_thClo[B_SZ * 128];
__device__ __align__(16) float g_h1 [B_SZ * HD];
__device__ __align__(16) float g_h2 [B_SZ * HD];
__device__ __align__(16) float g_mulv [B_SZ * 200];
__device__ __align__(16) float g_h1c[B_SZ * HD];
__device__ __align__(16) float g_h2c[B_SZ * HD];
__device__ __align__(16) float g_mulvc[B_SZ * 200];
__device__ __align__(16) float g_G  [NV_EN * KT];
__device__ __align__(16) float g_G2 [NV_CN * KT];
__device__ __align__(16) float g_recon [B_SZ * NV_EN];
__device__ __align__(16) float g_recon2[B_SZ * NV_CN];
__device__ __align__(16) float g_theta_en[B_SZ * KT];
__device__ __align__(16) float g_theta_cn[B_SZ * KT];
__device__ __align__(16) float g_wnorm [NV_EN];
__device__ __align__(16) float g_wnorm2[NV_CN];
__device__ __align__(16) float g_tnorm [KT];
__device__ __align__(16) float g_tnorm2[KT];
__device__ __align__(16) float g_tn[B_SZ * KT];
__device__ __align__(16) float g_tnT[KT * DE];
__device__ __align__(16) float g_C[KT * KT];
__device__ __align__(16) float g_cs [KT];
__device__ __align__(16) float g_cs2[KT];
__device__ __align__(16) float g_acc[8];

#define KC 32
#define AST 40

__device__ __forceinline__ void split2(float x, bf16& h, bf16& l) {
    h = __float2bfloat16(x);
    l = __float2bfloat16(x - __bfloat162float(h));
}
__device__ __forceinline__ void split2h(float x, fp16& h, fp16& l) {
    h = __float2half(x);
    l = __float2half(x - __half2float(h));
}

__device__ __forceinline__ void mma16816(float* c, const uint32_t* a, uint32_t b0, uint32_t b1) {
    asm volatile(
        "mma.sync.aligned.m16n8k16.row.col.f32.bf16.bf16.f32 "
        "{%0,%1,%2,%3}, {%4,%5,%6,%7}, {%8,%9}, {%0,%1,%2,%3};"
        : "+f"(c[0]), "+f"(c[1]), "+f"(c[2]), "+f"(c[3])
        : "r"(a[0]), "r"(a[1]), "r"(a[2]), "r"(a[3]), "r"(b0), "r"(b1));
}
__device__ __forceinline__ void mma16816h(float* c, const uint32_t* a, uint32_t b0, uint32_t b1) {
    asm volatile(
        "mma.sync.aligned.m16n8k16.row.col.f32.f16.f16.f32 "
        "{%0,%1,%2,%3}, {%4,%5,%6,%7}, {%8,%9}, {%0,%1,%2,%3};"
        : "+f"(c[0]), "+f"(c[1]), "+f"(c[2]), "+f"(c[3])
        : "r"(a[0]), "r"(a[1]), "r"(a[2]), "r"(a[3]), "r"(b0), "r"(b1));
}

// ======== split-bf16 GEMM (3 or 1 products) ========
template<int SPLIT>
__global__ __launch_bounds__(256)
void tc_gemm3(const bf16* __restrict__ Ahi, const bf16* __restrict__ Alo,
              const bf16* __restrict__ Bhi, const bf16* __restrict__ Blo,
              float* __restrict__ C, int M, int N, int Kp,
              int chunksPerZ, int mode)
{
    extern __shared__ __align__(16) bf16 smem[];
    const int TILE = 128 * AST;
    const int NT = SPLIT ? 4 : 2;
    const int STAGE = NT * TILE;

    int tid = threadIdx.x;
    int warp = tid >> 5, lane = tid & 31;
    int wm = warp >> 1, wn = warp & 1;
    int row0 = blockIdx.y * 128;
    int col0 = blockIdx.x * 128;
    int totalChunks = Kp / KC;
    int c0 = blockIdx.z * chunksPerZ;
    int nC = min(chunksPerZ, totalChunks - c0);
    if (nC <= 0) return;

    float acc[2][8][4];
#pragma unroll
    for (int i = 0; i < 2; i++)
#pragma unroll
        for (int j = 0; j < 8; j++)
#pragma unroll
            for (int q = 0; q < 4; q++) acc[i][j][q] = 0.f;

    int g = lane >> 2, t4 = lane & 3;

    auto issue_copy = [&](int s, int k0) {
#pragma unroll
        for (int it = 0; it < 2 * NT; it++) {
            const int t = it >> 1;
            int idx = ((it & 1) << 8) | tid;
            int r = idx >> 2, j = idx & 3;
            const bf16* src;
            int rb;
            if (SPLIT) {
                src = (t == 0) ? Ahi : (t == 1) ? Alo : (t == 2) ? Bhi : Blo;
                rb = (t < 2) ? row0 : col0;
            } else {
                src = (t == 0) ? Ahi : Bhi;
                rb = (t == 0) ? row0 : col0;
            }
            const bf16* gp = src + (size_t)(rb + r) * Kp + k0 + j * 8;
            bf16* dp = smem + s * STAGE + t * TILE + r * AST + j * 8;
            uint32_t da = (uint32_t)__cvta_generic_to_shared(dp);
            asm volatile("cp.async.cg.shared.global [%0], [%1], 16;" :: "r"(da), "l"(gp));
        }
        asm volatile("cp.async.commit_group;" ::: "memory");
    };

    issue_copy(0, c0 * KC);

    for (int lc = 0; lc < nC; lc++) {
        if (lc + 1 < nC) {
            issue_copy((lc + 1) & 1, (c0 + lc + 1) * KC);
            asm volatile("cp.async.wait_group 1;" ::: "memory");
        } else {
            asm volatile("cp.async.wait_group 0;" ::: "memory");
        }
        __syncthreads();

        const bf16* sAh = smem + (lc & 1) * STAGE;
        const bf16* sAl = sAh + TILE;
        const bf16* sBh = SPLIT ? (sAh + 2 * TILE) : (sAh + TILE);
        const bf16* sBl = sAh + 3 * TILE;

#pragma unroll
        for (int ks = 0; ks < 2; ks++) {
            int kb = ks * 16 + t4 * 2;
            uint32_t ah[2][4], al[2][4];
#pragma unroll
            for (int mf = 0; mf < 2; mf++) {
                int ar = wm * 32 + mf * 16 + g;
                int base = ar * AST + kb;
                ah[mf][0] = *reinterpret_cast<const uint32_t*>(&sAh[base]);
                ah[mf][1] = *reinterpret_cast<const uint32_t*>(&sAh[base + 8 * AST]);
                ah[mf][2] = *reinterpret_cast<const uint32_t*>(&sAh[base + 8]);
                ah[mf][3] = *reinterpret_cast<const uint32_t*>(&sAh[base + 8 * AST + 8]);
                if (SPLIT) {
                    al[mf][0] = *reinterpret_cast<const uint32_t*>(&sAl[base]);
                    al[mf][1] = *reinterpret_cast<const uint32_t*>(&sAl[base + 8 * AST]);
                    al[mf][2] = *reinterpret_cast<const uint32_t*>(&sAl[base + 8]);
                    al[mf][3] = *reinterpret_cast<const uint32_t*>(&sAl[base + 8 * AST + 8]);
                }
            }
#pragma unroll
            for (int nf = 0; nf < 8; nf++) {
                int bn = wn * 64 + nf * 8 + g;
                int bbase = bn * AST + kb;
                uint32_t bh0 = *reinterpret_cast<const uint32_t*>(&sBh[bbase]);
                uint32_t bh1 = *reinterpret_cast<const uint32_t*>(&sBh[bbase + 8]);
#pragma unroll
                for (int mf = 0; mf < 2; mf++)
                    mma16816(acc[mf][nf], ah[mf], bh0, bh1);
                if (SPLIT) {
                    uint32_t bl0 = *reinterpret_cast<const uint32_t*>(&sBl[bbase]);
                    uint32_t bl1 = *reinterpret_cast<const uint32_t*>(&sBl[bbase + 8]);
#pragma unroll
                    for (int mf = 0; mf < 2; mf++) {
                        mma16816(acc[mf][nf], ah[mf], bl0, bl1);
                        mma16816(acc[mf][nf], al[mf], bh0, bh1);
                    }
                }
            }
        }
        __syncthreads();
    }

#pragma unroll
    for (int mf = 0; mf < 2; mf++) {
#pragma unroll
        for (int nf = 0; nf < 8; nf++) {
            int r = row0 + wm * 32 + mf * 16 + g;
            int c = col0 + wn * 64 + nf * 8 + t4 * 2;
            float* a4 = acc[mf][nf];
#pragma unroll
            for (int h = 0; h < 2; h++) {
                int rr = r + h * 8;
                if (rr >= M) continue;
#pragma unroll
                for (int q = 0; q < 2; q++) {
                    int cc = c + q;
                    if (cc >= N) continue;
                    float v = a4[h * 2 + q];
                    if (mode) atomicAdd(&C[(size_t)rr * N + cc], v);
                    else C[(size_t)rr * N + cc] = v;
                }
            }
        }
    }
}

// ======== fp16 2-product GEMM: C = Ah[MxKp] @ (Bh+Bl)[NxKp]^T ========
// A is fp16 hi-only; B is fp16 hi/lo. 3 tiles/stage, 2 MMAs per fragment.
__global__ __launch_bounds__(256)
void tc_gemm_h2(const fp16* __restrict__ A, const fp16* __restrict__ Bh,
                const fp16* __restrict__ Bl, float* __restrict__ C,
                int M, int N, int Kp, int chunksPerZ, int mode)
{
    extern __shared__ __align__(16) fp16 smemh[];
    const int TILE = 128 * AST;
    const int STAGE = 3 * TILE;

    int tid = threadIdx.x;
    int warp = tid >> 5, lane = tid & 31;
    int wm = warp >> 1, wn = warp & 1;
    int row0 = blockIdx.y * 128;
    int col0 = blockIdx.x * 128;
    int totalChunks = Kp / KC;
    int c0 = blockIdx.z * chunksPerZ;
    int nC = min(chunksPerZ, totalChunks - c0);
    if (nC <= 0) return;

    float acc[2][8][4];
#pragma unroll
    for (int i = 0; i < 2; i++)
#pragma unroll
        for (int j = 0; j < 8; j++)
#pragma unroll
            for (int q = 0; q < 4; q++) acc[i][j][q] = 0.f;

    int g = lane >> 2, t4 = lane & 3;

    auto issue_copy = [&](int s, int k0) {
#pragma unroll
        for (int it = 0; it < 6; it++) {
            const int t = it >> 1;
            int idx = ((it & 1) << 8) | tid;
            int r = idx >> 2, j = idx & 3;
            const fp16* src = (t == 0) ? A : (t == 1) ? Bh : Bl;
            int rb = (t == 0) ? row0 : col0;
            const fp16* gp = src + (size_t)(rb + r) * Kp + k0 + j * 8;
            fp16* dp = smemh + s * STAGE + t * TILE + r * AST + j * 8;
            uint32_t da = (uint32_t)__cvta_generic_to_shared(dp);
            asm volatile("cp.async.cg.shared.global [%0], [%1], 16;" :: "r"(da), "l"(gp));
        }
        asm volatile("cp.async.commit_group;" ::: "memory");
    };

    issue_copy(0, c0 * KC);

    for (int lc = 0; lc < nC; lc++) {
        if (lc + 1 < nC) {
            issue_copy((lc + 1) & 1, (c0 + lc + 1) * KC);
            asm volatile("cp.async.wait_group 1;" ::: "memory");
        } else {
            asm volatile("cp.async.wait_group 0;" ::: "memory");
        }
        __syncthreads();

        const fp16* sA  = smemh + (lc & 1) * STAGE;
        const fp16* sBh = sA + TILE;
        const fp16* sBl = sA + 2 * TILE;

#pragma unroll
        for (int ks = 0; ks < 2; ks++) {
            int kb = ks * 16 + t4 * 2;
            uint32_t ah[2][4];
#pragma unroll
            for (int mf = 0; mf < 2; mf++) {
                int ar = wm * 32 + mf * 16 + g;
                int base = ar * AST + kb;
                ah[mf][0] = *reinterpret_cast<const uint32_t*>(&sA[base]);
                ah[mf][1] = *reinterpret_cast<const uint32_t*>(&sA[base + 8 * AST]);
                ah[mf][2] = *reinterpret_cast<const uint32_t*>(&sA[base + 8]);
                ah[mf][3] = *reinterpret_cast<const uint32_t*>(&sA[base + 8 * AST + 8]);
            }
#pragma unroll
            for (int nf = 0; nf < 8; nf++) {
                int bn = wn * 64 + nf * 8 + g;
                int bbase = bn * AST + kb;
                uint32_t bh0 = *reinterpret_cast<const uint32_t*>(&sBh[bbase]);
                uint32_t bh1 = *reinterpret_cast<const uint32_t*>(&sBh[bbase + 8]);
                uint32_t bl0 = *reinterpret_cast<const uint32_t*>(&sBl[bbase]);
                uint32_t bl1 = *reinterpret_cast<const uint32_t*>(&sBl[bbase + 8]);
#pragma unroll
                for (int mf = 0; mf < 2; mf++) {
                    mma16816h(acc[mf][nf], ah[mf], bh0, bh1);
                    mma16816h(acc[mf][nf], ah[mf], bl0, bl1);
                }
            }
        }
        __syncthreads();
    }

#pragma unroll
    for (int mf = 0; mf < 2; mf++) {
#pragma unroll
        for (int nf = 0; nf < 8; nf++) {
            int r = row0 + wm * 32 + mf * 16 + g;
            int c = col0 + wn * 64 + nf * 8 + t4 * 2;
            float* a4 = acc[mf][nf];
#pragma unroll
            for (int h = 0; h < 2; h++) {
                int rr = r + h * 8;
                if (rr >= M) continue;
#pragma unroll
                for (int q = 0; q < 2; q++) {
                    int cc = c + q;
                    if (cc >= N) continue;
                    float v = a4[h * 2 + q];
                    if (mode) atomicAdd(&C[(size_t)rr * N + cc], v);
                    else C[(size_t)rr * N + cc] = v;
                }
            }
        }
    }
}

// ---------------- conversions ----------------
__global__ void conv_pad(const float* __restrict__ src, bf16* __restrict__ hi, bf16* __restrict__ lo,
                         int R, int K, int Kp) {
    size_t total = (size_t)R * Kp;
    for (size_t idx = blockIdx.x * (size_t)blockDim.x + threadIdx.x; idx < total;
         idx += (size_t)gridDim.x * blockDim.x) {
        int r = (int)(idx / Kp), k = (int)(idx % Kp);
        float v = (k < K) ? src[(size_t)r * K + k] : 0.f;
        bf16 h, l; split2(v, h, l);
        hi[idx] = h; lo[idx] = l;
    }
}

// fp16 hi-only pad convert (for x operands)
__global__ void conv_f16hi(const float* __restrict__ src, fp16* __restrict__ hi,
                           int R, int K, int Kp) {
    size_t total = (size_t)R * Kp;
    for (size_t idx = blockIdx.x * (size_t)blockDim.x + threadIdx.x; idx < total;
         idx += (size_t)gridDim.x * blockDim.x) {
        int r = (int)(idx / Kp), k = (int)(idx % Kp);
        hi[idx] = __float2half((k < K) ? src[(size_t)r * K + k] : 0.f);
    }
}

__global__ void tconv(const float* __restrict__ src, bf16* __restrict__ hi, bf16* __restrict__ lo,
                      int R, int C, int Kp) {
    __shared__ float t[32][33];
    int kb = blockIdx.y * 32, nb = blockIdx.x * 32;
    int tx = threadIdx.x, ty = threadIdx.y;
#pragma unroll
    for (int i = 0; i < 4; i++) {
        int r = kb + ty + i * 8, c = nb + tx;
        t[ty + i * 8][tx] = (r < R && c < C) ? src[(size_t)r * C + c] : 0.f;
    }
    __syncthreads();
#pragma unroll
    for (int i = 0; i < 4; i++) {
        int n = nb + ty + i * 8, k = kb + tx;
        if (n < C && k < Kp) {
            bf16 h, l; split2(t[tx][ty + i * 8], h, l);
            hi[(size_t)n * Kp + k] = h;
            lo[(size_t)n * Kp + k] = l;
        }
    }
}

// fp16 split transpose-convert (for W1)
__global__ void tconv_f16(const float* __restrict__ src, fp16* __restrict__ hi, fp16* __restrict__ lo,
                          int R, int C, int Kp) {
    __shared__ float t[32][33];
    int kb = blockIdx.y * 32, nb = blockIdx.x * 32;
    int tx = threadIdx.x, ty = threadIdx.y;
#pragma unroll
    for (int i = 0; i < 4; i++) {
        int r = kb + ty + i * 8, c = nb + tx;
        t[ty + i * 8][tx] = (r < R && c < C) ? src[(size_t)r * C + c] : 0.f;
    }
    __syncthreads();
#pragma unroll
    for (int i = 0; i < 4; i++) {
        int n = nb + ty + i * 8, k = kb + tx;
        if (n < C && k < Kp) {
            fp16 h, l; split2h(t[tx][ty + i * 8], h, l);
            hi[(size_t)n * Kp + k] = h;
            lo[(size_t)n * Kp + k] = l;
        }
    }
}

__global__ void bias_sp_conv(const float* __restrict__ X, const float* __restrict__ bias,
                             bf16* __restrict__ hi, bf16* __restrict__ lo, int M, int N) {
    int total = M * N;
    for (int idx = blockIdx.x * blockDim.x + threadIdx.x; idx < total; idx += gridDim.x * blockDim.x) {
        int j = idx % N;
        float v = X[idx] + bias[j];
        float sp = fmaxf(v, 0.f) + log1pf(expf(-fabsf(v)));
        bf16 h, l; split2(sp, h, l);
        hi[idx] = h; lo[idx] = l;
    }
}

// ---------------- elementwise / reductions ----------------
__global__ void zero_kernel(float* p, int n) {
    for (int i = blockIdx.x * blockDim.x + threadIdx.x; i < n; i += gridDim.x * blockDim.x)
        p[i] = 0.f;
}

__global__ void theta_kl_kernel(const float* __restrict__ mulv,
                                const float* __restrict__ bmu, const float* __restrict__ blv,
                                const float* __restrict__ eps, float* __restrict__ theta_scratch,
                                float* __restrict__ theta_dout,
                                bf16* __restrict__ thi, bf16* __restrict__ tlo, float* kl_acc)
{
    int i = blockIdx.x;
    int k = threadIdx.x;
    __shared__ float red[128];
    float zv = -1e30f, kl = 0.f;
    if (k < KT) {
        float mu = mulv[i * 200 + k] + bmu[k];
        float lv = mulv[i * 200 + 100 + k] + blv[k];
        zv = mu + eps[i * KT + k] * expf(0.5f * lv);
        kl = expf(lv) + mu * mu - 1.f - lv;
    }
    red[k] = zv; __syncthreads();
    for (int s = 64; s > 0; s >>= 1) { if (k < s) red[k] = fmaxf(red[k], red[k + s]); __syncthreads(); }
    float m = red[0]; __syncthreads();
    float e = (k < KT) ? expf(zv - m) : 0.f;
    red[k] = e; __syncthreads();
    for (int s = 64; s > 0; s >>= 1) { if (k < s) red[k] += red[k + s]; __syncthreads(); }
    float ssum = red[0]; __syncthreads();
    {
        float t = (k < KT) ? (e / ssum) : 0.f;
        if (k < KT) {
            theta_scratch[i * KT + k] = t;
            theta_dout[i * KT + k] = t;
        }
        bf16 h, l; split2(t, h, l);
        thi[i * 128 + k] = h;
        tlo[i * 128 + k] = l;
    }
    red[k] = (k < KT) ? kl : 0.f; __syncthreads();
    for (int s = 64; s > 0; s >>= 1) { if (k < s) red[k] += red[k + s]; __syncthreads(); }
    if (k == 0) atomicAdd(kl_acc, 0.5f * red[0]);
}

__global__ void rownorm2_kernel(const float* __restrict__ X, float* __restrict__ out, int R, int D) {
    int warp = (blockIdx.x * blockDim.x + threadIdx.x) >> 5;
    int lane = threadIdx.x & 31;
    if (warp >= R) return;
    float s = 0.f;
    for (int d = lane; d < D; d += 32) { float v = X[(size_t)warp * D + d]; s = fmaf(v, v, s); }
    for (int o = 16; o; o >>= 1) s += __shfl_down_sync(0xffffffffu, s, o);
    if (lane == 0) out[warp] = s;
}

__global__ void beta_pass1(const float* __restrict__ G, const float* __restrict__ wnorm,
                           const float* __restrict__ tnorm, float* __restrict__ beta_dout,
                           float* __restrict__ colsum, int V)
{
    __shared__ float tn_s[KT];
    __shared__ float wsum[8];
    int v = blockIdx.x * 256 + threadIdx.x;
    if (threadIdx.x < KT) tn_s[threadIdx.x] = tnorm[threadIdx.x];
    __syncthreads();
    bool ok = v < V;
    float wn = ok ? wnorm[v] : 0.f;
    int lane = threadIdx.x & 31, wid = threadIdx.x >> 5;
    for (int k = 0; k < KT; k++) {
        float e = 0.f;
        if (ok) {
            float sq = wn + tn_s[k] - 2.f * G[(size_t)v * KT + k];
            float d = sqrtf(fmaxf(sq, 0.f));
            e = expf(-d / TAU_);
            beta_dout[(size_t)k * V + v] = e;
        }
        float s = e;
        for (int o = 16; o; o >>= 1) s += __shfl_down_sync(0xffffffffu, s, o);
        if (lane == 0) wsum[wid] = s;
        __syncthreads();
        if (threadIdx.x == 0) {
            float t = 0.f;
            for (int w = 0; w < 8; w++) t += wsum[w];
            atomicAdd(&colsum[k], t);
        }
        __syncthreads();
    }
}

__global__ void beta_pass2(float* __restrict__ beta_dout, const float* __restrict__ colsum, int V) {
    int total = KT * V;
    for (int idx = blockIdx.x * blockDim.x + threadIdx.x; idx < total; idx += gridDim.x * blockDim.x) {
        int k = idx / V;
        beta_dout[idx] = beta_dout[idx] / colsum[k];
    }
}

__global__ void recon_loss_kernel(const float* __restrict__ x, const float* __restrict__ recon,
                                  int V, float* acc)
{
    int i = blockIdx.x;
    int tid = threadIdx.x;
    float m = -1e30f, s = 0.f, dot = 0.f, sx = 0.f;
    for (int v = tid; v < V; v += 256) {
        float r = recon[(size_t)i * V + v];
        float xv = x[(size_t)i * V + v];
        if (r > m) { s = s * expf(m - r) + 1.f; m = r; }
        else s += expf(r - m);
        dot = fmaf(xv, r, dot);
        sx += xv;
    }
    __shared__ float sm[256], ss[256], sd[256], sxs[256];
    sm[tid] = m; ss[tid] = s; sd[tid] = dot; sxs[tid] = sx;
    __syncthreads();
    for (int o = 128; o; o >>= 1) {
        if (tid < o) {
            float m1 = sm[tid], s1 = ss[tid];
            float m2 = sm[tid + o], s2 = ss[tid + o];
            float M_ = fmaxf(m1, m2);
            sm[tid] = M_;
            ss[tid] = s1 * expf(m1 - M_) + s2 * expf(m2 - M_);
            sd[tid] += sd[tid + o];
            sxs[tid] += sxs[tid + o];
        }
        __syncthreads();
    }
    if (tid == 0) {
        float lse = sm[0] + logf(ss[0]);
        atomicAdd(acc, -sd[0] + sxs[0] * lse);
    }
}

__global__ void select_norm_kernel(const float* __restrict__ theta_en,
                                   const float* __restrict__ theta_cn, float* __restrict__ tn)
{
    int i = blockIdx.x;
    int k = threadIdx.x;
    __shared__ float red[128];
    const float* src = ((i & 1) == 0) ? theta_en : theta_cn;
    float v = (k < KT) ? src[i * KT + k] : 0.f;
    red[k] = v * v; __syncthreads();
    for (int s = 64; s > 0; s >>= 1) { if (k < s) red[k] += red[k + s]; __syncthreads(); }
    float nrm = fmaxf(sqrtf(red[0]), 1e-8f);
    if (k < KT) tn[i * KT + k] = v / nrm;
}

__global__ void contrast_kernel(const float* __restrict__ tn, const int* __restrict__ cid, float* acc)
{
    int i = blockIdx.x;
    int tid = threadIdx.x;
    __shared__ float ti[KT];
    if (tid < KT) ti[tid] = tn[i * KT + tid];
    __syncthreads();
    int ci = cid[i];
    bool vi = ci > 0;
    float pos = 0.f, neg = 0.f, pcnt = 0.f;
    for (int j = tid; j < B_SZ; j += 256) {
        if (j == i) continue;
        float s = 0.f;
        const float* tj = &tn[j * KT];
#pragma unroll 4
        for (int k = 0; k < KT; k++) s = fmaf(ti[k], tj[k], s);
        float E = expf(s / TAU_);
        neg += E;
        int cj = cid[j];
        if (vi && cj > 0 && cj == ci) { pos += E; pcnt += 1.f; }
    }
    __shared__ float r1[256], r2[256], r3[256];
    r1[tid] = pos; r2[tid] = neg; r3[tid] = pcnt;
    __syncthreads();
    for (int o = 128; o; o >>= 1) {
        if (tid < o) { r1[tid] += r1[tid + o]; r2[tid] += r2[tid + o]; r3[tid] += r3[tid + o]; }
        __syncthreads();
    }
    if (tid == 0) {
        if (vi && r3[0] > 0.5f) {
            float per = -logf(r1[0] / (r1[0] + r2[0] + 1e-8f));
            atomicAdd(&acc[4], per);
            atomicAdd(&acc[5], 1.f);
        }
    }
}

__global__ void norm_topic_kernel(const float* __restrict__ T, float* __restrict__ Tn) {
    int k = blockIdx.x;
    int d = threadIdx.x;
    __shared__ float red[128];
    float s = 0.f;
    for (int dd = d; dd < DE; dd += 128) { float v = T[k * DE + dd]; s = fmaf(v, v, s); }
    red[d] = s; __syncthreads();
    for (int o = 64; o > 0; o >>= 1) { if (d < o) red[d] += red[d + o]; __syncthreads(); }
    float nrm = fmaxf(sqrtf(red[0]), 1e-8f);
    for (int dd = d; dd < DE; dd += 128) Tn[k * DE + dd] = T[k * DE + dd] / nrm;
}

__global__ void cmat_kernel(const float* __restrict__ Tn, float* __restrict__ C) {
    int i = blockIdx.x;
    __shared__ float ti[DE];
    for (int d = threadIdx.x; d < DE; d += 128) ti[d] = Tn[i * DE + d];
    __syncthreads();
    for (int j = threadIdx.x; j < KT; j += 128) {
        float s = 0.f;
        for (int d = 0; d < DE; d++) s = fmaf(ti[d], Tn[j * DE + d], s);
        C[i * KT + j] = 1.f - s;
    }
}

__global__ void sinkhorn_kernel(const float* __restrict__ C, float* acc) {
    __shared__ float Ks[KT * KT];
    __shared__ float u[KT], v[KT];
    __shared__ float red[256];
    int tid = threadIdx.x;
    for (int idx = tid; idx < KT * KT; idx += 256) Ks[idx] = expf(-C[idx] / EPS_SK);
    if (tid < KT) { u[tid] = 1.f; v[tid] = 1.f; }
    __syncthreads();
    const float a = 1.f / KT;
    for (int it = 0; it < 50; it++) {
        if (tid < KT) {
            float d = 1e-8f;
            for (int j = 0; j < KT; j++) d = fmaf(Ks[tid * KT + j], v[j], d);
            u[tid] = a / d;
        }
        __syncthreads();
        if (tid < KT) {
            float d = 1e-8f;
            for (int i2 = 0; i2 < KT; i2++) d = fmaf(Ks[i2 * KT + tid], u[i2], d);
            v[tid] = a / d;
        }
        __syncthreads();
    }
    float s = 0.f;
    for (int idx = tid; idx < KT * KT; idx += 256) {
        int i2 = idx / KT, j = idx % KT;
        s += u[i2] * Ks[idx] * v[j] * C[idx];
    }
    red[tid] = s; __syncthreads();
    for (int o = 128; o; o >>= 1) { if (tid < o) red[tid] += red[tid + o]; __syncthreads(); }
    if (tid == 0) acc[6] = red[0];
}

__global__ void finalize_kernel(const float* __restrict__ acc, float* __restrict__ out) {
    float tm_en = acc[0] / (float)B_SZ + acc[1] / (float)B_SZ;
    float tm_cn = acc[2] / (float)B_SZ + acc[3] / (float)B_SZ;
    float contrast = acc[4] / (acc[5] + 1e-8f);
    float align = acc[6];
    out[0] = tm_en + tm_cn + contrast + align;
    out[1] = tm_en;
    out[2] = tm_cn;
    out[3] = contrast;
    out[4] = align;
}

// ---------------- host ----------------
template<int SPLIT>
static inline void launch_tc3(const bf16* Ah, const bf16* Al, const bf16* Bh, const bf16* Bl,
                              float* C, int M, int N, int Kp, int z, int mode, cudaStream_t st)
{
    size_t sm = (size_t)(SPLIT ? 4 : 2) * 2 * 128 * AST * sizeof(bf16);
    cudaFuncSetAttribute(tc_gemm3<SPLIT>, cudaFuncAttributeMaxDynamicSharedMemorySize, 98304);
    int total = Kp / KC;
    int per = (total + z - 1) / z;
    dim3 g((N + 127) / 128, (M + 127) / 128, z);
    tc_gemm3<SPLIT><<<g, 256, sm, st>>>(Ah, Al, Bh, Bl, C, M, N, Kp, per, mode);
}

static inline void launch_tch2(const fp16* A, const fp16* Bh, const fp16* Bl,
                               float* C, int M, int N, int Kp, int z, int mode, cudaStream_t st)
{
    size_t sm = (size_t)3 * 2 * 128 * AST * sizeof(fp16);
    cudaFuncSetAttribute(tc_gemm_h2, cudaFuncAttributeMaxDynamicSharedMemorySize, 98304);
    int total = Kp / KC;
    int per = (total + z - 1) / z;
    dim3 g((N + 127) / 128, (M + 127) / 128, z);
    tc_gemm_h2<<<g, 256, sm, st>>>(A, Bh, Bl, C, M, N, Kp, per, mode);
}

extern "C" void kernel_launch(void* const* d_in, const int* in_sizes, int n_in,
                              void* d_out, int out_size)
{
    const float* x_en   = (const float*)d_in[0];
    const float* x_cn   = (const float*)d_in[1];
    const int*   cid    = (const int*)  d_in[2];
    const float* eps_en = (const float*)d_in[3];
    const float* eps_cn = (const float*)d_in[4];
    const float* W1_en  = (const float*)d_in[5];
    const float* b1_en  = (const float*)d_in[6];
    const float* W2_en  = (const float*)d_in[7];
    const float* b2_en  = (const float*)d_in[8];
    const float* Wmu_en = (const float*)d_in[9];
    const float* bmu_en = (const float*)d_in[10];
    const float* Wlv_en = (const float*)d_in[11];
    const float* blv_en = (const float*)d_in[12];
    const float* W1_cn  = (const float*)d_in[13];
    const float* b1_cn  = (const float*)d_in[14];
    const float* W2_cn  = (const float*)d_in[15];
    const float* b2_cn  = (const float*)d_in[16];
    const float* Wmu_cn = (const float*)d_in[17];
    const float* bmu_cn = (const float*)d_in[18];
    const float* Wlv_cn = (const float*)d_in[19];
    const float* blv_cn = (const float*)d_in[20];
    const float* we_en  = (const float*)d_in[21];
    const float* we_cn  = (const float*)d_in[22];
    const float* topic  = (const float*)d_in[23];

    float* out = (float*)d_out;
    float* theta_en_out = out + 5;
    float* theta_cn_out = theta_en_out + B_SZ * KT;
    float* beta_en_out  = theta_cn_out + B_SZ * KT;
    float* beta_cn_out  = beta_en_out + KT * NV_EN;

    static cudaStream_t s1 = nullptr, s2 = nullptr, s3 = nullptr;
    static cudaEvent_t eF, eMt, e1t, e2e, e3e, eW1E, eWsmE, eW1C, eWsmC;
    if (!s1) {
        cudaStreamCreateWithFlags(&s1, cudaStreamNonBlocking);
        cudaStreamCreateWithFlags(&s2, cudaStreamNonBlocking);
        cudaStreamCreateWithFlags(&s3, cudaStreamNonBlocking);
        cudaEventCreateWithFlags(&eF,   cudaEventDisableTiming);
        cudaEventCreateWithFlags(&eMt,  cudaEventDisableTiming);
        cudaEventCreateWithFlags(&e1t,  cudaEventDisableTiming);
        cudaEventCreateWithFlags(&e2e,  cudaEventDisableTiming);
        cudaEventCreateWithFlags(&e3e,  cudaEventDisableTiming);
        cudaEventCreateWithFlags(&eW1E, cudaEventDisableTiming);
        cudaEventCreateWithFlags(&eWsmE, cudaEventDisableTiming);
        cudaEventCreateWithFlags(&eW1C, cudaEventDisableTiming);
        cudaEventCreateWithFlags(&eWsmC, cudaEventDisableTiming);
    }

    float *h1, *h2, *mulv, *h1c, *h2c, *mulvc, *G, *G2, *recon, *recon2,
          *th_en, *th_cn, *wn, *wn2, *tnm, *tnm2, *tnb, *tnT, *Cm, *cs, *cs2, *acc;
    bf16 *Ahi, *Bhi, *Blo, *Ahs, *Alo, *A2hi, *B2hi, *B2lo, *A2hs, *A2lo,
         *W2Ehi, *W2Elo, *MVEhi, *MVElo, *W2Chi, *W2Clo, *MVChi, *MVClo,
         *WEhi, *WElo, *Thi, *Tlo, *BEhi, *BElo, *thEhi, *thElo,
         *WChi, *WClo, *T2hi, *T2lo, *BChi, *BClo, *thChi, *thClo;
    cudaGetSymbolAddress((void**)&Ahi,   g_Ahi);
    cudaGetSymbolAddress((void**)&Bhi,   g_Bhi);   cudaGetSymbolAddress((void**)&Blo,   g_Blo);
    cudaGetSymbolAddress((void**)&Ahs,   g_Ahs);   cudaGetSymbolAddress((void**)&Alo,   g_Alo);
    cudaGetSymbolAddress((void**)&A2hi,  g_A2hi);
    cudaGetSymbolAddress((void**)&B2hi,  g_B2hi);  cudaGetSymbolAddress((void**)&B2lo,  g_B2lo);
    cudaGetSymbolAddress((void**)&A2hs,  g_A2hs);  cudaGetSymbolAddress((void**)&A2lo,  g_A2lo);
    cudaGetSymbolAddress((void**)&W2Ehi, g_W2Ehi); cudaGetSymbolAddress((void**)&W2Elo, g_W2Elo);
    cudaGetSymbolAddress((void**)&MVEhi, g_MVEhi); cudaGetSymbolAddress((void**)&MVElo, g_MVElo);
    cudaGetSymbolAddress((void**)&W2Chi, g_W2Chi); cudaGetSymbolAddress((void**)&W2Clo, g_W2Clo);
    cudaGetSymbolAddress((void**)&MVChi, g_MVChi); cudaGetSymbolAddress((void**)&MVClo, g_MVClo);
    cudaGetSymbolAddress((void**)&WEhi,  g_WEhi);  cudaGetSymbolAddress((void**)&WElo,  g_WElo);
    cudaGetSymbolAddress((void**)&Thi,   g_Thi);   cudaGetSymbolAddress((void**)&Tlo,   g_Tlo);
    cudaGetSymbolAddress((void**)&BEhi,  g_BEhi);  cudaGetSymbolAddress((void**)&BElo,  g_BElo);
    cudaGetSymbolAddress((void**)&thEhi, g_thEhi); cudaGetSymbolAddress((void**)&thElo, g_thElo);
    cudaGetSymbolAddress((void**)&WChi,  g_WChi);  cudaGetSymbolAddress((void**)&WClo,  g_WClo);
    cudaGetSymbolAddress((void**)&T2hi,  g_T2hi);  cudaGetSymbolAddress((void**)&T2lo,  g_T2lo);
    cudaGetSymbolAddress((void**)&BChi,  g_BChi);  cudaGetSymbolAddress((void**)&BClo,  g_BClo);
    cudaGetSymbolAddress((void**)&thChi, g_thChi); cudaGetSymbolAddress((void**)&thClo, g_thClo);
    cudaGetSymbolAddress((void**)&h1,    g_h1);    cudaGetSymbolAddress((void**)&h2,    g_h2);
    cudaGetSymbolAddress((void**)&mulv,  g_mulv);
    cudaGetSymbolAddress((void**)&h1c,   g_h1c);   cudaGetSymbolAddress((void**)&h2c,   g_h2c);
    cudaGetSymbolAddress((void**)&mulvc, g_mulvc);
    cudaGetSymbolAddress((void**)&G,     g_G);     cudaGetSymbolAddress((void**)&G2,    g_G2);
    cudaGetSymbolAddress((void**)&recon, g_recon); cudaGetSymbolAddress((void**)&recon2, g_recon2);
    cudaGetSymbolAddress((void**)&th_en, g_theta_en);
    cudaGetSymbolAddress((void**)&th_cn, g_theta_cn);
    cudaGetSymbolAddress((void**)&wn,    g_wnorm); cudaGetSymbolAddress((void**)&wn2,   g_wnorm2);
    cudaGetSymbolAddress((void**)&tnm,   g_tnorm); cudaGetSymbolAddress((void**)&tnm2,  g_tnorm2);
    cudaGetSymbolAddress((void**)&tnb,   g_tn);
    cudaGetSymbolAddress((void**)&tnT,   g_tnT);
    cudaGetSymbolAddress((void**)&Cm,    g_C);
    cudaGetSymbolAddress((void**)&cs,    g_cs);    cudaGetSymbolAddress((void**)&cs2,   g_cs2);
    cudaGetSymbolAddress((void**)&acc,   g_acc);

    fp16* xEh  = (fp16*)Ahi;   fp16* W1Eh = (fp16*)Bhi;  fp16* W1El = (fp16*)Blo;
    fp16* xCh  = (fp16*)A2hi;  fp16* W1Ch = (fp16*)B2hi; fp16* W1Cl = (fp16*)B2lo;

    dim3 tb(32, 8);

    // ---- fork ----
    zero_kernel<<<1, 64>>>(acc, 8);
    cudaEventRecord(eF, 0);
    cudaStreamWaitEvent(s1, eF, 0);
    cudaStreamWaitEvent(s2, eF, 0);
    cudaStreamWaitEvent(s3, eF, 0);

    // ======== stream s2: EN weight conversions, then beta EN ========
    tconv_f16<<<dim3(16, 938), tb, 0, s2>>>(W1_en, W1Eh, W1El, NV_EN, HD, KP_EN);
    cudaEventRecord(eW1E, s2);
    tconv<<<dim3(16, 16), tb, 0, s2>>>(W2_en, W2Ehi, W2Elo, HD, HD, 512);
    tconv<<<dim3(4, 16), tb, 0, s2>>>(Wmu_en, MVEhi, MVElo, HD, KT, 512);
    tconv<<<dim3(4, 16), tb, 0, s2>>>(Wlv_en, MVEhi + 100 * 512, MVElo + 100 * 512, HD, KT, 512);
    cudaEventRecord(eWsmE, s2);
    rownorm2_kernel<<<(NV_EN * 32 + 255) / 256, 256, 0, s2>>>(we_en, wn, NV_EN, DE);
    rownorm2_kernel<<<(KT * 32 + 255) / 256, 256, 0, s2>>>(topic, tnm, KT, DE);
    conv_pad<<<256, 256, 0, s2>>>(topic, Thi, Tlo, KT, DE, 320);
    conv_pad<<<4096, 256, 0, s2>>>(we_en, WEhi, WElo, NV_EN, DE, 320);
    launch_tc3<1>(WEhi, WElo, Thi, Tlo, G, NV_EN, KT, 320, 1, 0, s2);
    zero_kernel<<<1, 128, 0, s2>>>(cs, KT);
    beta_pass1<<<(NV_EN + 255) / 256, 256, 0, s2>>>(G, wn, tnm, beta_en_out, cs, NV_EN);
    beta_pass2<<<2048, 256, 0, s2>>>(beta_en_out, cs, NV_EN);
    tconv<<<dim3(938, 4), tb, 0, s2>>>(beta_en_out, BEhi, BElo, KT, NV_EN, 128);

    // ======== stream s3: CN weight conversions, then beta CN ========
    tconv_f16<<<dim3(16, 626), tb, 0, s3>>>(W1_cn, W1Ch, W1Cl, NV_CN, HD, KP_CN);
    cudaEventRecord(eW1C, s3);
    tconv<<<dim3(16, 16), tb, 0, s3>>>(W2_cn, W2Chi, W2Clo, HD, HD, 512);
    tconv<<<dim3(4, 16), tb, 0, s3>>>(Wmu_cn, MVChi, MVClo, HD, KT, 512);
    tconv<<<dim3(4, 16), tb, 0, s3>>>(Wlv_cn, MVChi + 100 * 512, MVClo + 100 * 512, HD, KT, 512);
    cudaEventRecord(eWsmC, s3);
    rownorm2_kernel<<<(NV_CN * 32 + 255) / 256, 256, 0, s3>>>(we_cn, wn2, NV_CN, DE);
    rownorm2_kernel<<<(KT * 32 + 255) / 256, 256, 0, s3>>>(topic, tnm2, KT, DE);
    conv_pad<<<256, 256, 0, s3>>>(topic, T2hi, T2lo, KT, DE, 320);
    conv_pad<<<4096, 256, 0, s3>>>(we_cn, WChi, WClo, NV_CN, DE, 320);
    launch_tc3<1>(WChi, WClo, T2hi, T2lo, G2, NV_CN, KT, 320, 1, 0, s3);
    zero_kernel<<<1, 128, 0, s3>>>(cs2, KT);
    beta_pass1<<<(NV_CN + 255) / 256, 256, 0, s3>>>(G2, wn2, tnm2, beta_cn_out, cs2, NV_CN);
    beta_pass2<<<2048, 256, 0, s3>>>(beta_cn_out, cs2, NV_CN);
    tconv<<<dim3(626, 4), tb, 0, s3>>>(beta_cn_out, BChi, BClo, KT, NV_CN, 128);

    // ======== stream 0: EN encoder ========
    zero_kernel<<<1024, 256>>>(h1, B_SZ * HD);
    zero_kernel<<<1024, 256>>>(h2, B_SZ * HD);
    zero_kernel<<<512, 256>>>(mulv, B_SZ * 200);
    conv_f16hi<<<4096, 256>>>(x_en, xEh, B_SZ, NV_EN, KP_EN);
    cudaStreamWaitEvent(0, eW1E, 0);
    launch_tch2(xEh, W1Eh, W1El, h1, B_SZ, HD, KP_EN, 16, 1, 0);
    bias_sp_conv<<<1024, 256>>>(h1, b1_en, Ahs, Alo, B_SZ, HD);
    cudaStreamWaitEvent(0, eWsmE, 0);
    launch_tc3<1>(Ahs, Alo, W2Ehi, W2Elo, h2, B_SZ, HD, 512, 8, 1, 0);
    bias_sp_conv<<<1024, 256>>>(h2, b2_en, Ahs, Alo, B_SZ, HD);
    launch_tc3<1>(Ahs, Alo, MVEhi, MVElo, mulv, B_SZ, 200, 512, 8, 1, 0);
    theta_kl_kernel<<<B_SZ, 128>>>(mulv, bmu_en, blv_en, eps_en, th_en, theta_en_out, thEhi, thElo, acc + 1);
    cudaEventRecord(eMt, 0);

    // ======== stream s1: CN encoder ========
    zero_kernel<<<1024, 256, 0, s1>>>(h1c, B_SZ * HD);
    zero_kernel<<<1024, 256, 0, s1>>>(h2c, B_SZ * HD);
    zero_kernel<<<512, 256, 0, s1>>>(mulvc, B_SZ * 200);
    conv_f16hi<<<4096, 256, 0, s1>>>(x_cn, xCh, B_SZ, NV_CN, KP_CN);
    cudaStreamWaitEvent(s1, eW1C, 0);
    launch_tch2(xCh, W1Ch, W1Cl, h1c, B_SZ, HD, KP_CN, 16, 1, s1);
    bias_sp_conv<<<1024, 256, 0, s1>>>(h1c, b1_cn, A2hs, A2lo, B_SZ, HD);
    cudaStreamWaitEvent(s1, eWsmC, 0);
    launch_tc3<1>(A2hs, A2lo, W2Chi, W2Clo, h2c, B_SZ, HD, 512, 8, 1, s1);
    bias_sp_conv<<<1024, 256, 0, s1>>>(h2c, b2_cn, A2hs, A2lo, B_SZ, HD);
    launch_tc3<1>(A2hs, A2lo, MVChi, MVClo, mulvc, B_SZ, 200, 512, 8, 1, s1);
    theta_kl_kernel<<<B_SZ, 128, 0, s1>>>(mulvc, bmu_cn, blv_cn, eps_cn, th_cn, theta_cn_out, thChi, thClo, acc + 3);
    cudaEventRecord(e1t, s1);

    // ======== recon tails ========
    cudaStreamWaitEvent(s2, eMt, 0);
    launch_tc3<0>(thEhi, thElo, BEhi, BElo, recon, B_SZ, NV_EN, 128, 1, 0, s2);
    recon_loss_kernel<<<B_SZ, 256, 0, s2>>>(x_en, recon, NV_EN, acc + 0);
    cudaEventRecord(e2e, s2);

    cudaStreamWaitEvent(s3, e1t, 0);
    launch_tc3<0>(thChi, thClo, BChi, BClo, recon2, B_SZ, NV_CN, 128, 1, 0, s3);
    recon_loss_kernel<<<B_SZ, 256, 0, s3>>>(x_cn, recon2, NV_CN, acc + 2);
    cudaEventRecord(e3e, s3);

    // ======== stream 0: alignment, contrastive, join ========
    norm_topic_kernel<<<KT, 128>>>(topic, tnT);
    cmat_kernel<<<KT, 128>>>(tnT, Cm);
    sinkhorn_kernel<<<1, 256>>>(Cm, acc);
    cudaStreamWaitEvent(0, e1t, 0);
    select_norm_kernel<<<B_SZ, 128>>>(th_en, th_cn, tnb);
    contrast_kernel<<<B_SZ, 256>>>(tnb, cid, acc);
    cudaStreamWaitEvent(0, e2e, 0);
    cudaStreamWaitEvent(0, e3e, 0);
    finalize_kernel<<<1, 1>>>(acc, out);
}

// round 16
// speedup vs baseline: 1.3460x; 1.1561x over previous
#include <cuda_runtime.h>
#include <cuda_bf16.h>
#include <cuda_fp16.h>
#include <math.h>
#include <stdint.h>

#define B_SZ 512
#define NV_EN 30000
#define NV_CN 20000
#define KT 100
#define HD 512
#define DE 300
#define TAU_ 1.0f
#define EPS_SK 0.1f

#define KP_EN 30016
#define KP_CN 20032
#define GR_EN 30080
#define GR_CN 20096

typedef __nv_bfloat16 bf16;
typedef __half fp16;

// ---------------- device scratch ----------------
__device__ __align__(16) bf16 g_Ahi[B_SZ * KP_EN];     // fp16 x_en
__device__ __align__(16) bf16 g_Bhi[B_SZ * KP_EN];     // fp16 W1_en hi
__device__ __align__(16) bf16 g_Alo[B_SZ * HD];
__device__ __align__(16) bf16 g_Ahs[B_SZ * HD];
__device__ __align__(16) bf16 g_A2hi[B_SZ * KP_CN];    // fp16 x_cn
__device__ __align__(16) bf16 g_B2hi[B_SZ * KP_CN];    // fp16 W1_cn hi
__device__ __align__(16) bf16 g_A2lo[B_SZ * HD];
__device__ __align__(16) bf16 g_A2hs[B_SZ * HD];
__device__ __align__(16) bf16 g_W2Ehi[512 * 512];
__device__ __align__(16) bf16 g_W2Elo[512 * 512];
__device__ __align__(16) bf16 g_MVEhi[256 * 512];
__device__ __align__(16) bf16 g_MVElo[256 * 512];
__device__ __align__(16) bf16 g_W2Chi[512 * 512];
__device__ __align__(16) bf16 g_W2Clo[512 * 512];
__device__ __align__(16) bf16 g_MVChi[256 * 512];
__device__ __align__(16) bf16 g_MVClo[256 * 512];
__device__ __align__(16) bf16 g_WEhi[GR_EN * 320];     // fp16 we_en
__device__ __align__(16) bf16 g_Thi [128 * 320];       // fp16 topic hi
__device__ __align__(16) bf16 g_Tlo [128 * 320];       // fp16 topic lo
__device__ __align__(16) bf16 g_BEhi[GR_EN * 128];
__device__ __align__(16) bf16 g_BElo[GR_EN * 128];
__device__ __align__(16) bf16 g_thEhi[B_SZ * 128];
__device__ __align__(16) bf16 g_thElo[B_SZ * 128];
__device__ __align__(16) bf16 g_WChi[GR_CN * 320];     // fp16 we_cn
__device__ __align__(16) bf16 g_T2hi[128 * 320];
__device__ __align__(16) bf16 g_T2lo[128 * 320];
__device__ __align__(16) bf16 g_BChi[GR_CN * 128];
__device__ __align__(16) bf16 g_BClo[GR_CN * 128];
__device__ __align__(16) bf16 g_thChi[B_SZ * 128];
__device__ __align__(16) bf16 g_thClo[B_SZ * 128];
__device__ __align__(16) float g_h1 [B_SZ * HD];
__device__ __align__(16) float g_h2 [B_SZ * HD];
__device__ __align__(16) float g_mulv [B_SZ * 200];
__device__ __align__(16) float g_h1c[B_SZ * HD];
__device__ __align__(16) float g_h2c[B_SZ * HD];
__device__ __align__(16) float g_mulvc[B_SZ * 200];
__device__ __align__(16) float g_G  [NV_EN * KT];
__device__ __align__(16) float g_G2 [NV_CN * KT];
__device__ __align__(16) float g_recon [B_SZ * NV_EN];
__device__ __align__(16) float g_recon2[B_SZ * NV_CN];
__device__ __align__(16) float g_theta_en[B_SZ * KT];
__device__ __align__(16) float g_theta_cn[B_SZ * KT];
__device__ __align__(16) float g_wnorm [NV_EN];
__device__ __align__(16) float g_wnorm2[NV_CN];
__device__ __align__(16) float g_tnorm [KT];
__device__ __align__(16) float g_tnorm2[KT];
__device__ __align__(16) float g_tn[B_SZ * KT];
__device__ __align__(16) float g_tnT[KT * DE];
__device__ __align__(16) float g_C[KT * KT];
__device__ __align__(16) float g_cs [KT];
__device__ __align__(16) float g_cs2[KT];
__device__ __align__(16) float g_acc[8];

#define KC 32
#define AST 40

__device__ __forceinline__ void split2(float x, bf16& h, bf16& l) {
    h = __float2bfloat16(x);
    l = __float2bfloat16(x - __bfloat162float(h));
}
__device__ __forceinline__ void split2h(float x, fp16& h, fp16& l) {
    h = __float2half(x);
    l = __float2half(x - __half2float(h));
}

__device__ __forceinline__ void mma16816(float* c, const uint32_t* a, uint32_t b0, uint32_t b1) {
    asm volatile(
        "mma.sync.aligned.m16n8k16.row.col.f32.bf16.bf16.f32 "
        "{%0,%1,%2,%3}, {%4,%5,%6,%7}, {%8,%9}, {%0,%1,%2,%3};"
        : "+f"(c[0]), "+f"(c[1]), "+f"(c[2]), "+f"(c[3])
        : "r"(a[0]), "r"(a[1]), "r"(a[2]), "r"(a[3]), "r"(b0), "r"(b1));
}
__device__ __forceinline__ void mma16816h(float* c, const uint32_t* a, uint32_t b0, uint32_t b1) {
    asm volatile(
        "mma.sync.aligned.m16n8k16.row.col.f32.f16.f16.f32 "
        "{%0,%1,%2,%3}, {%4,%5,%6,%7}, {%8,%9}, {%0,%1,%2,%3};"
        : "+f"(c[0]), "+f"(c[1]), "+f"(c[2]), "+f"(c[3])
        : "r"(a[0]), "r"(a[1]), "r"(a[2]), "r"(a[3]), "r"(b0), "r"(b1));
}

// ======== split-bf16 GEMM (3 or 1 products) ========
template<int SPLIT>
__global__ __launch_bounds__(256)
void tc_gemm3(const bf16* __restrict__ Ahi, const bf16* __restrict__ Alo,
              const bf16* __restrict__ Bhi, const bf16* __restrict__ Blo,
              float* __restrict__ C, int M, int N, int Kp,
              int chunksPerZ, int mode)
{
    extern __shared__ __align__(16) bf16 smem[];
    const int TILE = 128 * AST;
    const int NT = SPLIT ? 4 : 2;
    const int STAGE = NT * TILE;

    int tid = threadIdx.x;
    int warp = tid >> 5, lane = tid & 31;
    int wm = warp >> 1, wn = warp & 1;
    int row0 = blockIdx.y * 128;
    int col0 = blockIdx.x * 128;
    int totalChunks = Kp / KC;
    int c0 = blockIdx.z * chunksPerZ;
    int nC = min(chunksPerZ, totalChunks - c0);
    if (nC <= 0) return;

    float acc[2][8][4];
#pragma unroll
    for (int i = 0; i < 2; i++)
#pragma unroll
        for (int j = 0; j < 8; j++)
#pragma unroll
            for (int q = 0; q < 4; q++) acc[i][j][q] = 0.f;

    int g = lane >> 2, t4 = lane & 3;

    auto issue_copy = [&](int s, int k0) {
#pragma unroll
        for (int it = 0; it < 2 * NT; it++) {
            const int t = it >> 1;
            int idx = ((it & 1) << 8) | tid;
            int r = idx >> 2, j = idx & 3;
            const bf16* src;
            int rb;
            if (SPLIT) {
                src = (t == 0) ? Ahi : (t == 1) ? Alo : (t == 2) ? Bhi : Blo;
                rb = (t < 2) ? row0 : col0;
            } else {
                src = (t == 0) ? Ahi : Bhi;
                rb = (t == 0) ? row0 : col0;
            }
            const bf16* gp = src + (size_t)(rb + r) * Kp + k0 + j * 8;
            bf16* dp = smem + s * STAGE + t * TILE + r * AST + j * 8;
            uint32_t da = (uint32_t)__cvta_generic_to_shared(dp);
            asm volatile("cp.async.cg.shared.global [%0], [%1], 16;" :: "r"(da), "l"(gp));
        }
        asm volatile("cp.async.commit_group;" ::: "memory");
    };

    issue_copy(0, c0 * KC);

    for (int lc = 0; lc < nC; lc++) {
        if (lc + 1 < nC) {
            issue_copy((lc + 1) & 1, (c0 + lc + 1) * KC);
            asm volatile("cp.async.wait_group 1;" ::: "memory");
        } else {
            asm volatile("cp.async.wait_group 0;" ::: "memory");
        }
        __syncthreads();

        const bf16* sAh = smem + (lc & 1) * STAGE;
        const bf16* sAl = sAh + TILE;
        const bf16* sBh = SPLIT ? (sAh + 2 * TILE) : (sAh + TILE);
        const bf16* sBl = sAh + 3 * TILE;

#pragma unroll
        for (int ks = 0; ks < 2; ks++) {
            int kb = ks * 16 + t4 * 2;
            uint32_t ah[2][4], al[2][4];
#pragma unroll
            for (int mf = 0; mf < 2; mf++) {
                int ar = wm * 32 + mf * 16 + g;
                int base = ar * AST + kb;
                ah[mf][0] = *reinterpret_cast<const uint32_t*>(&sAh[base]);
                ah[mf][1] = *reinterpret_cast<const uint32_t*>(&sAh[base + 8 * AST]);
                ah[mf][2] = *reinterpret_cast<const uint32_t*>(&sAh[base + 8]);
                ah[mf][3] = *reinterpret_cast<const uint32_t*>(&sAh[base + 8 * AST + 8]);
                if (SPLIT) {
                    al[mf][0] = *reinterpret_cast<const uint32_t*>(&sAl[base]);
                    al[mf][1] = *reinterpret_cast<const uint32_t*>(&sAl[base + 8 * AST]);
                    al[mf][2] = *reinterpret_cast<const uint32_t*>(&sAl[base + 8]);
                    al[mf][3] = *reinterpret_cast<const uint32_t*>(&sAl[base + 8 * AST + 8]);
                }
            }
#pragma unroll
            for (int nf = 0; nf < 8; nf++) {
                int bn = wn * 64 + nf * 8 + g;
                int bbase = bn * AST + kb;
                uint32_t bh0 = *reinterpret_cast<const uint32_t*>(&sBh[bbase]);
                uint32_t bh1 = *reinterpret_cast<const uint32_t*>(&sBh[bbase + 8]);
#pragma unroll
                for (int mf = 0; mf < 2; mf++)
                    mma16816(acc[mf][nf], ah[mf], bh0, bh1);
                if (SPLIT) {
                    uint32_t bl0 = *reinterpret_cast<const uint32_t*>(&sBl[bbase]);
                    uint32_t bl1 = *reinterpret_cast<const uint32_t*>(&sBl[bbase + 8]);
#pragma unroll
                    for (int mf = 0; mf < 2; mf++) {
                        mma16816(acc[mf][nf], ah[mf], bl0, bl1);
                        mma16816(acc[mf][nf], al[mf], bh0, bh1);
                    }
                }
            }
        }
        __syncthreads();
    }

#pragma unroll
    for (int mf = 0; mf < 2; mf++) {
#pragma unroll
        for (int nf = 0; nf < 8; nf++) {
            int r = row0 + wm * 32 + mf * 16 + g;
            int c = col0 + wn * 64 + nf * 8 + t4 * 2;
            float* a4 = acc[mf][nf];
#pragma unroll
            for (int h = 0; h < 2; h++) {
                int rr = r + h * 8;
                if (rr >= M) continue;
#pragma unroll
                for (int q = 0; q < 2; q++) {
                    int cc = c + q;
                    if (cc >= N) continue;
                    float v = a4[h * 2 + q];
                    if (mode) atomicAdd(&C[(size_t)rr * N + cc], v);
                    else C[(size_t)rr * N + cc] = v;
                }
            }
        }
    }
}

// ======== fp16 GEMM: C = Ah @ Bh^T (+ Ah @ Bl^T if SPLITB) ========
template<int SPLITB>
__global__ __launch_bounds__(256)
void tc_gemm_h(const fp16* __restrict__ A, const fp16* __restrict__ Bh,
               const fp16* __restrict__ Bl, float* __restrict__ C,
               int M, int N, int Kp, int chunksPerZ, int mode)
{
    extern __shared__ __align__(16) fp16 smemh[];
    const int TILE = 128 * AST;
    const int NT = 2 + SPLITB;
    const int STAGE = NT * TILE;

    int tid = threadIdx.x;
    int warp = tid >> 5, lane = tid & 31;
    int wm = warp >> 1, wn = warp & 1;
    int row0 = blockIdx.y * 128;
    int col0 = blockIdx.x * 128;
    int totalChunks = Kp / KC;
    int c0 = blockIdx.z * chunksPerZ;
    int nC = min(chunksPerZ, totalChunks - c0);
    if (nC <= 0) return;

    float acc[2][8][4];
#pragma unroll
    for (int i = 0; i < 2; i++)
#pragma unroll
        for (int j = 0; j < 8; j++)
#pragma unroll
            for (int q = 0; q < 4; q++) acc[i][j][q] = 0.f;

    int g = lane >> 2, t4 = lane & 3;

    auto issue_copy = [&](int s, int k0) {
#pragma unroll
        for (int it = 0; it < 2 * NT; it++) {
            const int t = it >> 1;
            int idx = ((it & 1) << 8) | tid;
            int r = idx >> 2, j = idx & 3;
            const fp16* src = (t == 0) ? A : (t == 1) ? Bh : Bl;
            int rb = (t == 0) ? row0 : col0;
            const fp16* gp = src + (size_t)(rb + r) * Kp + k0 + j * 8;
            fp16* dp = smemh + s * STAGE + t * TILE + r * AST + j * 8;
            uint32_t da = (uint32_t)__cvta_generic_to_shared(dp);
            asm volatile("cp.async.cg.shared.global [%0], [%1], 16;" :: "r"(da), "l"(gp));
        }
        asm volatile("cp.async.commit_group;" ::: "memory");
    };

    issue_copy(0, c0 * KC);

    for (int lc = 0; lc < nC; lc++) {
        if (lc + 1 < nC) {
            issue_copy((lc + 1) & 1, (c0 + lc + 1) * KC);
            asm volatile("cp.async.wait_group 1;" ::: "memory");
        } else {
            asm volatile("cp.async.wait_group 0;" ::: "memory");
        }
        __syncthreads();

        const fp16* sA  = smemh + (lc & 1) * STAGE;
        const fp16* sBh = sA + TILE;
        const fp16* sBl = sA + 2 * TILE;

#pragma unroll
        for (int ks = 0; ks < 2; ks++) {
            int kb = ks * 16 + t4 * 2;
            uint32_t ah[2][4];
#pragma unroll
            for (int mf = 0; mf < 2; mf++) {
                int ar = wm * 32 + mf * 16 + g;
                int base = ar * AST + kb;
                ah[mf][0] = *reinterpret_cast<const uint32_t*>(&sA[base]);
                ah[mf][1] = *reinterpret_cast<const uint32_t*>(&sA[base + 8 * AST]);
                ah[mf][2] = *reinterpret_cast<const uint32_t*>(&sA[base + 8]);
                ah[mf][3] = *reinterpret_cast<const uint32_t*>(&sA[base + 8 * AST + 8]);
            }
#pragma unroll
            for (int nf = 0; nf < 8; nf++) {
                int bn = wn * 64 + nf * 8 + g;
                int bbase = bn * AST + kb;
                uint32_t bh0 = *reinterpret_cast<const uint32_t*>(&sBh[bbase]);
                uint32_t bh1 = *reinterpret_cast<const uint32_t*>(&sBh[bbase + 8]);
#pragma unroll
                for (int mf = 0; mf < 2; mf++)
                    mma16816h(acc[mf][nf], ah[mf], bh0, bh1);
                if (SPLITB) {
                    uint32_t bl0 = *reinterpret_cast<const uint32_t*>(&sBl[bbase]);
                    uint32_t bl1 = *reinterpret_cast<const uint32_t*>(&sBl[bbase + 8]);
#pragma unroll
                    for (int mf = 0; mf < 2; mf++)
                        mma16816h(acc[mf][nf], ah[mf], bl0, bl1);
                }
            }
        }
        __syncthreads();
    }

#pragma unroll
    for (int mf = 0; mf < 2; mf++) {
#pragma unroll
        for (int nf = 0; nf < 8; nf++) {
            int r = row0 + wm * 32 + mf * 16 + g;
            int c = col0 + wn * 64 + nf * 8 + t4 * 2;
            float* a4 = acc[mf][nf];
#pragma unroll
            for (int h = 0; h < 2; h++) {
                int rr = r + h * 8;
                if (rr >= M) continue;
#pragma unroll
                for (int q = 0; q < 2; q++) {
                    int cc = c + q;
                    if (cc >= N) continue;
                    float v = a4[h * 2 + q];
                    if (mode) atomicAdd(&C[(size_t)rr * N + cc], v);
                    else C[(size_t)rr * N + cc] = v;
                }
            }
        }
    }
}

// ---------------- conversions ----------------
__global__ void conv_pad(const float* __restrict__ src, bf16* __restrict__ hi, bf16* __restrict__ lo,
                         int R, int K, int Kp) {
    size_t total = (size_t)R * Kp;
    for (size_t idx = blockIdx.x * (size_t)blockDim.x + threadIdx.x; idx < total;
         idx += (size_t)gridDim.x * blockDim.x) {
        int r = (int)(idx / Kp), k = (int)(idx % Kp);
        float v = (k < K) ? src[(size_t)r * K + k] : 0.f;
        bf16 h, l; split2(v, h, l);
        hi[idx] = h; lo[idx] = l;
    }
}

__global__ void conv_f16hi(const float* __restrict__ src, fp16* __restrict__ hi,
                           int R, int K, int Kp) {
    size_t total = (size_t)R * Kp;
    for (size_t idx = blockIdx.x * (size_t)blockDim.x + threadIdx.x; idx < total;
         idx += (size_t)gridDim.x * blockDim.x) {
        int r = (int)(idx / Kp), k = (int)(idx % Kp);
        hi[idx] = __float2half((k < K) ? src[(size_t)r * K + k] : 0.f);
    }
}

// fp16 hi/lo pad split (non-transposed), e.g. topic [N,K]
__global__ void conv_f16split(const float* __restrict__ src, fp16* __restrict__ hi,
                              fp16* __restrict__ lo, int R, int K, int Kp) {
    size_t total = (size_t)R * Kp;
    for (size_t idx = blockIdx.x * (size_t)blockDim.x + threadIdx.x; idx < total;
         idx += (size_t)gridDim.x * blockDim.x) {
        int r = (int)(idx / Kp), k = (int)(idx % Kp);
        float v = (k < K) ? src[(size_t)r * K + k] : 0.f;
        fp16 h, l; split2h(v, h, l);
        hi[idx] = h; lo[idx] = l;
    }
}

__global__ void tconv(const float* __restrict__ src, bf16* __restrict__ hi, bf16* __restrict__ lo,
                      int R, int C, int Kp) {
    __shared__ float t[32][33];
    int kb = blockIdx.y * 32, nb = blockIdx.x * 32;
    int tx = threadIdx.x, ty = threadIdx.y;
#pragma unroll
    for (int i = 0; i < 4; i++) {
        int r = kb + ty + i * 8, c = nb + tx;
        t[ty + i * 8][tx] = (r < R && c < C) ? src[(size_t)r * C + c] : 0.f;
    }
    __syncthreads();
#pragma unroll
    for (int i = 0; i < 4; i++) {
        int n = nb + ty + i * 8, k = kb + tx;
        if (n < C && k < Kp) {
            bf16 h, l; split2(t[tx][ty + i * 8], h, l);
            hi[(size_t)n * Kp + k] = h;
            lo[(size_t)n * Kp + k] = l;
        }
    }
}

// fp16 hi-only transpose-convert (for W1)
__global__ void tconv_f16hi(const float* __restrict__ src, fp16* __restrict__ hi,
                            int R, int C, int Kp) {
    __shared__ float t[32][33];
    int kb = blockIdx.y * 32, nb = blockIdx.x * 32;
    int tx = threadIdx.x, ty = threadIdx.y;
#pragma unroll
    for (int i = 0; i < 4; i++) {
        int r = kb + ty + i * 8, c = nb + tx;
        t[ty + i * 8][tx] = (r < R && c < C) ? src[(size_t)r * C + c] : 0.f;
    }
    __syncthreads();
#pragma unroll
    for (int i = 0; i < 4; i++) {
        int n = nb + ty + i * 8, k = kb + tx;
        if (n < C && k < Kp)
            hi[(size_t)n * Kp + k] = __float2half(t[tx][ty + i * 8]);
    }
}

__global__ void bias_sp_conv(const float* __restrict__ X, const float* __restrict__ bias,
                             bf16* __restrict__ hi, bf16* __restrict__ lo, int M, int N) {
    int total = M * N;
    for (int idx = blockIdx.x * blockDim.x + threadIdx.x; idx < total; idx += gridDim.x * blockDim.x) {
        int j = idx % N;
        float v = X[idx] + bias[j];
        float sp = fmaxf(v, 0.f) + log1pf(expf(-fabsf(v)));
        bf16 h, l; split2(sp, h, l);
        hi[idx] = h; lo[idx] = l;
    }
}

// ---------------- elementwise / reductions ----------------
__global__ void zero_kernel(float* p, int n) {
    for (int i = blockIdx.x * blockDim.x + threadIdx.x; i < n; i += gridDim.x * blockDim.x)
        p[i] = 0.f;
}

__global__ void theta_kl_kernel(const float* __restrict__ mulv,
                                const float* __restrict__ bmu, const float* __restrict__ blv,
                                const float* __restrict__ eps, float* __restrict__ theta_scratch,
                                float* __restrict__ theta_dout,
                                bf16* __restrict__ thi, bf16* __restrict__ tlo, float* kl_acc)
{
    int i = blockIdx.x;
    int k = threadIdx.x;
    __shared__ float red[128];
    float zv = -1e30f, kl = 0.f;
    if (k < KT) {
        float mu = mulv[i * 200 + k] + bmu[k];
        float lv = mulv[i * 200 + 100 + k] + blv[k];
        zv = mu + eps[i * KT + k] * expf(0.5f * lv);
        kl = expf(lv) + mu * mu - 1.f - lv;
    }
    red[k] = zv; __syncthreads();
    for (int s = 64; s > 0; s >>= 1) { if (k < s) red[k] = fmaxf(red[k], red[k + s]); __syncthreads(); }
    float m = red[0]; __syncthreads();
    float e = (k < KT) ? expf(zv - m) : 0.f;
    red[k] = e; __syncthreads();
    for (int s = 64; s > 0; s >>= 1) { if (k < s) red[k] += red[k + s]; __syncthreads(); }
    float ssum = red[0]; __syncthreads();
    {
        float t = (k < KT) ? (e / ssum) : 0.f;
        if (k < KT) {
            theta_scratch[i * KT + k] = t;
            theta_dout[i * KT + k] = t;
        }
        bf16 h, l; split2(t, h, l);
        thi[i * 128 + k] = h;
        tlo[i * 128 + k] = l;
    }
    red[k] = (k < KT) ? kl : 0.f; __syncthreads();
    for (int s = 64; s > 0; s >>= 1) { if (k < s) red[k] += red[k + s]; __syncthreads(); }
    if (k == 0) atomicAdd(kl_acc, 0.5f * red[0]);
}

__global__ void rownorm2_kernel(const float* __restrict__ X, float* __restrict__ out, int R, int D) {
    int warp = (blockIdx.x * blockDim.x + threadIdx.x) >> 5;
    int lane = threadIdx.x & 31;
    if (warp >= R) return;
    float s = 0.f;
    for (int d = lane; d < D; d += 32) { float v = X[(size_t)warp * D + d]; s = fmaf(v, v, s); }
    for (int o = 16; o; o >>= 1) s += __shfl_down_sync(0xffffffffu, s, o);
    if (lane == 0) out[warp] = s;
}

__global__ void beta_pass1(const float* __restrict__ G, const float* __restrict__ wnorm,
                           const float* __restrict__ tnorm, float* __restrict__ beta_dout,
                           float* __restrict__ colsum, int V)
{
    __shared__ float tn_s[KT];
    __shared__ float wsum[8];
    int v = blockIdx.x * 256 + threadIdx.x;
    if (threadIdx.x < KT) tn_s[threadIdx.x] = tnorm[threadIdx.x];
    __syncthreads();
    bool ok = v < V;
    float wn = ok ? wnorm[v] : 0.f;
    int lane = threadIdx.x & 31, wid = threadIdx.x >> 5;
    for (int k = 0; k < KT; k++) {
        float e = 0.f;
        if (ok) {
            float sq = wn + tn_s[k] - 2.f * G[(size_t)v * KT + k];
            float d = sqrtf(fmaxf(sq, 0.f));
            e = expf(-d / TAU_);
            beta_dout[(size_t)k * V + v] = e;
        }
        float s = e;
        for (int o = 16; o; o >>= 1) s += __shfl_down_sync(0xffffffffu, s, o);
        if (lane == 0) wsum[wid] = s;
        __syncthreads();
        if (threadIdx.x == 0) {
            float t = 0.f;
            for (int w = 0; w < 8; w++) t += wsum[w];
            atomicAdd(&colsum[k], t);
        }
        __syncthreads();
    }
}

__global__ void beta_pass2(float* __restrict__ beta_dout, const float* __restrict__ colsum, int V) {
    int total = KT * V;
    for (int idx = blockIdx.x * blockDim.x + threadIdx.x; idx < total; idx += gridDim.x * blockDim.x) {
        int k = idx / V;
        beta_dout[idx] = beta_dout[idx] / colsum[k];
    }
}

__global__ void recon_loss_kernel(const float* __restrict__ x, const float* __restrict__ recon,
                                  int V, float* acc)
{
    int i = blockIdx.x;
    int tid = threadIdx.x;
    float m = -1e30f, s = 0.f, dot = 0.f, sx = 0.f;
    for (int v = tid; v < V; v += 256) {
        float r = recon[(size_t)i * V + v];
        float xv = x[(size_t)i * V + v];
        if (r > m) { s = s * expf(m - r) + 1.f; m = r; }
        else s += expf(r - m);
        dot = fmaf(xv, r, dot);
        sx += xv;
    }
    __shared__ float sm[256], ss[256], sd[256], sxs[256];
    sm[tid] = m; ss[tid] = s; sd[tid] = dot; sxs[tid] = sx;
    __syncthreads();
    for (int o = 128; o; o >>= 1) {
        if (tid < o) {
            float m1 = sm[tid], s1 = ss[tid];
            float m2 = sm[tid + o], s2 = ss[tid + o];
            float M_ = fmaxf(m1, m2);
            sm[tid] = M_;
            ss[tid] = s1 * expf(m1 - M_) + s2 * expf(m2 - M_);
            sd[tid] += sd[tid + o];
            sxs[tid] += sxs[tid + o];
        }
        __syncthreads();
    }
    if (tid == 0) {
        float lse = sm[0] + logf(ss[0]);
        atomicAdd(acc, -sd[0] + sxs[0] * lse);
    }
}

__global__ void select_norm_kernel(const float* __restrict__ theta_en,
                                   const float* __restrict__ theta_cn, float* __restrict__ tn)
{
    int i = blockIdx.x;
    int k = threadIdx.x;
    __shared__ float red[128];
    const float* src = ((i & 1) == 0) ? theta_en : theta_cn;
    float v = (k < KT) ? src[i * KT + k] : 0.f;
    red[k] = v * v; __syncthreads();
    for (int s = 64; s > 0; s >>= 1) { if (k < s) red[k] += red[k + s]; __syncthreads(); }
    float nrm = fmaxf(sqrtf(red[0]), 1e-8f);
    if (k < KT) tn[i * KT + k] = v / nrm;
}

__global__ void contrast_kernel(const float* __restrict__ tn, const int* __restrict__ cid, float* acc)
{
    int i = blockIdx.x;
    int tid = threadIdx.x;
    __shared__ float ti[KT];
    if (tid < KT) ti[tid] = tn[i * KT + tid];
    __syncthreads();
    int ci = cid[i];
    bool vi = ci > 0;
    float pos = 0.f, neg = 0.f, pcnt = 0.f;
    for (int j = tid; j < B_SZ; j += 256) {
        if (j == i) continue;
        float s = 0.f;
        const float* tj = &tn[j * KT];
#pragma unroll 4
        for (int k = 0; k < KT; k++) s = fmaf(ti[k], tj[k], s);
        float E = expf(s / TAU_);
        neg += E;
        int cj = cid[j];
        if (vi && cj > 0 && cj == ci) { pos += E; pcnt += 1.f; }
    }
    __shared__ float r1[256], r2[256], r3[256];
    r1[tid] = pos; r2[tid] = neg; r3[tid] = pcnt;
    __syncthreads();
    for (int o = 128; o; o >>= 1) {
        if (tid < o) { r1[tid] += r1[tid + o]; r2[tid] += r2[tid + o]; r3[tid] += r3[tid + o]; }
        __syncthreads();
    }
    if (tid == 0) {
        if (vi && r3[0] > 0.5f) {
            float per = -logf(r1[0] / (r1[0] + r2[0] + 1e-8f));
            atomicAdd(&acc[4], per);
            atomicAdd(&acc[5], 1.f);
        }
    }
}

__global__ void norm_topic_kernel(const float* __restrict__ T, float* __restrict__ Tn) {
    int k = blockIdx.x;
    int d = threadIdx.x;
    __shared__ float red[128];
    float s = 0.f;
    for (int dd = d; dd < DE; dd += 128) { float v = T[k * DE + dd]; s = fmaf(v, v, s); }
    red[d] = s; __syncthreads();
    for (int o = 64; o > 0; o >>= 1) { if (d < o) red[d] += red[d + o]; __syncthreads(); }
    float nrm = fmaxf(sqrtf(red[0]), 1e-8f);
    for (int dd = d; dd < DE; dd += 128) Tn[k * DE + dd] = T[k * DE + dd] / nrm;
}

__global__ void cmat_kernel(const float* __restrict__ Tn, float* __restrict__ C) {
    int i = blockIdx.x;
    __shared__ float ti[DE];
    for (int d = threadIdx.x; d < DE; d += 128) ti[d] = Tn[i * DE + d];
    __syncthreads();
    for (int j = threadIdx.x; j < KT; j += 128) {
        float s = 0.f;
        for (int d = 0; d < DE; d++) s = fmaf(ti[d], Tn[j * DE + d], s);
        C[i * KT + j] = 1.f - s;
    }
}

__global__ void sinkhorn_kernel(const float* __restrict__ C, float* acc) {
    __shared__ float Ks[KT * KT];
    __shared__ float u[KT], v[KT];
    __shared__ float red[256];
    int tid = threadIdx.x;
    for (int idx = tid; idx < KT * KT; idx += 256) Ks[idx] = expf(-C[idx] / EPS_SK);
    if (tid < KT) { u[tid] = 1.f; v[tid] = 1.f; }
    __syncthreads();
    const float a = 1.f / KT;
    for (int it = 0; it < 50; it++) {
        if (tid < KT) {
            float d = 1e-8f;
            for (int j = 0; j < KT; j++) d = fmaf(Ks[tid * KT + j], v[j], d);
            u[tid] = a / d;
        }
        __syncthreads();
        if (tid < KT) {
            float d = 1e-8f;
            for (int i2 = 0; i2 < KT; i2++) d = fmaf(Ks[i2 * KT + tid], u[i2], d);
            v[tid] = a / d;
        }
        __syncthreads();
    }
    float s = 0.f;
    for (int idx = tid; idx < KT * KT; idx += 256) {
        int i2 = idx / KT, j = idx % KT;
        s += u[i2] * Ks[idx] * v[j] * C[idx];
    }
    red[tid] = s; __syncthreads();
    for (int o = 128; o; o >>= 1) { if (tid < o) red[tid] += red[tid + o]; __syncthreads(); }
    if (tid == 0) acc[6] = red[0];
}

__global__ void finalize_kernel(const float* __restrict__ acc, float* __restrict__ out) {
    float tm_en = acc[0] / (float)B_SZ + acc[1] / (float)B_SZ;
    float tm_cn = acc[2] / (float)B_SZ + acc[3] / (float)B_SZ;
    float contrast = acc[4] / (acc[5] + 1e-8f);
    float align = acc[6];
    out[0] = tm_en + tm_cn + contrast + align;
    out[1] = tm_en;
    out[2] = tm_cn;
    out[3] = contrast;
    out[4] = align;
}

// ---------------- host ----------------
template<int SPLIT>
static inline void launch_tc3(const bf16* Ah, const bf16* Al, const bf16* Bh, const bf16* Bl,
                              float* C, int M, int N, int Kp, int z, int mode, cudaStream_t st)
{
    size_t sm = (size_t)(SPLIT ? 4 : 2) * 2 * 128 * AST * sizeof(bf16);
    cudaFuncSetAttribute(tc_gemm3<SPLIT>, cudaFuncAttributeMaxDynamicSharedMemorySize, 98304);
    int total = Kp / KC;
    int per = (total + z - 1) / z;
    dim3 g((N + 127) / 128, (M + 127) / 128, z);
    tc_gemm3<SPLIT><<<g, 256, sm, st>>>(Ah, Al, Bh, Bl, C, M, N, Kp, per, mode);
}

template<int SPLITB>
static inline void launch_tch(const fp16* A, const fp16* Bh, const fp16* Bl,
                              float* C, int M, int N, int Kp, int z, int mode, cudaStream_t st)
{
    size_t sm = (size_t)(2 + SPLITB) * 2 * 128 * AST * sizeof(fp16);
    cudaFuncSetAttribute(tc_gemm_h<SPLITB>, cudaFuncAttributeMaxDynamicSharedMemorySize, 98304);
    int total = Kp / KC;
    int per = (total + z - 1) / z;
    dim3 g((N + 127) / 128, (M + 127) / 128, z);
    tc_gemm_h<SPLITB><<<g, 256, sm, st>>>(A, Bh, Bl, C, M, N, Kp, per, mode);
}

extern "C" void kernel_launch(void* const* d_in, const int* in_sizes, int n_in,
                              void* d_out, int out_size)
{
    const float* x_en   = (const float*)d_in[0];
    const float* x_cn   = (const float*)d_in[1];
    const int*   cid    = (const int*)  d_in[2];
    const float* eps_en = (const float*)d_in[3];
    const float* eps_cn = (const float*)d_in[4];
    const float* W1_en  = (const float*)d_in[5];
    const float* b1_en  = (const float*)d_in[6];
    const float* W2_en  = (const float*)d_in[7];
    const float* b2_en  = (const float*)d_in[8];
    const float* Wmu_en = (const float*)d_in[9];
    const float* bmu_en = (const float*)d_in[10];
    const float* Wlv_en = (const float*)d_in[11];
    const float* blv_en = (const float*)d_in[12];
    const float* W1_cn  = (const float*)d_in[13];
    const float* b1_cn  = (const float*)d_in[14];
    const float* W2_cn  = (const float*)d_in[15];
    const float* b2_cn  = (const float*)d_in[16];
    const float* Wmu_cn = (const float*)d_in[17];
    const float* bmu_cn = (const float*)d_in[18];
    const float* Wlv_cn = (const float*)d_in[19];
    const float* blv_cn = (const float*)d_in[20];
    const float* we_en  = (const float*)d_in[21];
    const float* we_cn  = (const float*)d_in[22];
    const float* topic  = (const float*)d_in[23];

    float* out = (float*)d_out;
    float* theta_en_out = out + 5;
    float* theta_cn_out = theta_en_out + B_SZ * KT;
    float* beta_en_out  = theta_cn_out + B_SZ * KT;
    float* beta_cn_out  = beta_en_out + KT * NV_EN;

    static cudaStream_t s1 = nullptr, s2 = nullptr, s3 = nullptr;
    static cudaEvent_t eF, eMt, e1t, e2e, e3e, eW1E, eWsmE, eW1C, eWsmC;
    if (!s1) {
        cudaStreamCreateWithFlags(&s1, cudaStreamNonBlocking);
        cudaStreamCreateWithFlags(&s2, cudaStreamNonBlocking);
        cudaStreamCreateWithFlags(&s3, cudaStreamNonBlocking);
        cudaEventCreateWithFlags(&eF,   cudaEventDisableTiming);
        cudaEventCreateWithFlags(&eMt,  cudaEventDisableTiming);
        cudaEventCreateWithFlags(&e1t,  cudaEventDisableTiming);
        cudaEventCreateWithFlags(&e2e,  cudaEventDisableTiming);
        cudaEventCreateWithFlags(&e3e,  cudaEventDisableTiming);
        cudaEventCreateWithFlags(&eW1E, cudaEventDisableTiming);
        cudaEventCreateWithFlags(&eWsmE, cudaEventDisableTiming);
        cudaEventCreateWithFlags(&eW1C, cudaEventDisableTiming);
        cudaEventCreateWithFlags(&eWsmC, cudaEventDisableTiming);
    }

    float *h1, *h2, *mulv, *h1c, *h2c, *mulvc, *G, *G2, *recon, *recon2,
          *th_en, *th_cn, *wn, *wn2, *tnm, *tnm2, *tnb, *tnT, *Cm, *cs, *cs2, *acc;
    bf16 *Ahi, *Bhi, *Ahs, *Alo, *A2hi, *B2hi, *A2hs, *A2lo,
         *W2Ehi, *W2Elo, *MVEhi, *MVElo, *W2Chi, *W2Clo, *MVChi, *MVClo,
         *WEhi, *Thi, *Tlo, *BEhi, *BElo, *thEhi, *thElo,
         *WChi, *T2hi, *T2lo, *BChi, *BClo, *thChi, *thClo;
    cudaGetSymbolAddress((void**)&Ahi,   g_Ahi);
    cudaGetSymbolAddress((void**)&Bhi,   g_Bhi);
    cudaGetSymbolAddress((void**)&Ahs,   g_Ahs);   cudaGetSymbolAddress((void**)&Alo,   g_Alo);
    cudaGetSymbolAddress((void**)&A2hi,  g_A2hi);
    cudaGetSymbolAddress((void**)&B2hi,  g_B2hi);
    cudaGetSymbolAddress((void**)&A2hs,  g_A2hs);  cudaGetSymbolAddress((void**)&A2lo,  g_A2lo);
    cudaGetSymbolAddress((void**)&W2Ehi, g_W2Ehi); cudaGetSymbolAddress((void**)&W2Elo, g_W2Elo);
    cudaGetSymbolAddress((void**)&MVEhi, g_MVEhi); cudaGetSymbolAddress((void**)&MVElo, g_MVElo);
    cudaGetSymbolAddress((void**)&W2Chi, g_W2Chi); cudaGetSymbolAddress((void**)&W2Clo, g_W2Clo);
    cudaGetSymbolAddress((void**)&MVChi, g_MVChi); cudaGetSymbolAddress((void**)&MVClo, g_MVClo);
    cudaGetSymbolAddress((void**)&WEhi,  g_WEhi);
    cudaGetSymbolAddress((void**)&Thi,   g_Thi);   cudaGetSymbolAddress((void**)&Tlo,   g_Tlo);
    cudaGetSymbolAddress((void**)&BEhi,  g_BEhi);  cudaGetSymbolAddress((void**)&BElo,  g_BElo);
    cudaGetSymbolAddress((void**)&thEhi, g_thEhi); cudaGetSymbolAddress((void**)&thElo, g_thElo);
    cudaGetSymbolAddress((void**)&WChi,  g_WChi);
    cudaGetSymbolAddress((void**)&T2hi,  g_T2hi);  cudaGetSymbolAddress((void**)&T2lo,  g_T2lo);
    cudaGetSymbolAddress((void**)&BChi,  g_BChi);  cudaGetSymbolAddress((void**)&BClo,  g_BClo);
    cudaGetSymbolAddress((void**)&thChi, g_thChi); cudaGetSymbolAddress((void**)&thClo, g_thClo);
    cudaGetSymbolAddress((void**)&h1,    g_h1);    cudaGetSymbolAddress((void**)&h2,    g_h2);
    cudaGetSymbolAddress((void**)&mulv,  g_mulv);
    cudaGetSymbolAddress((void**)&h1c,   g_h1c);   cudaGetSymbolAddress((void**)&h2c,   g_h2c);
    cudaGetSymbolAddress((void**)&mulvc, g_mulvc);
    cudaGetSymbolAddress((void**)&G,     g_G);     cudaGetSymbolAddress((void**)&G2,    g_G2);
    cudaGetSymbolAddress((void**)&recon, g_recon); cudaGetSymbolAddress((void**)&recon2, g_recon2);
    cudaGetSymbolAddress((void**)&th_en, g_theta_en);
    cudaGetSymbolAddress((void**)&th_cn, g_theta_cn);
    cudaGetSymbolAddress((void**)&wn,    g_wnorm); cudaGetSymbolAddress((void**)&wn2,   g_wnorm2);
    cudaGetSymbolAddress((void**)&tnm,   g_tnorm); cudaGetSymbolAddress((void**)&tnm2,  g_tnorm2);
    cudaGetSymbolAddress((void**)&tnb,   g_tn);
    cudaGetSymbolAddress((void**)&tnT,   g_tnT);
    cudaGetSymbolAddress((void**)&Cm,    g_C);
    cudaGetSymbolAddress((void**)&cs,    g_cs);    cudaGetSymbolAddress((void**)&cs2,   g_cs2);
    cudaGetSymbolAddress((void**)&acc,   g_acc);

    fp16* xEh  = (fp16*)Ahi;   fp16* W1Eh = (fp16*)Bhi;
    fp16* xCh  = (fp16*)A2hi;  fp16* W1Ch = (fp16*)B2hi;
    fp16* weEh = (fp16*)WEhi;  fp16* tEh  = (fp16*)Thi;  fp16* tEl  = (fp16*)Tlo;
    fp16* weCh = (fp16*)WChi;  fp16* tCh  = (fp16*)T2hi; fp16* tCl  = (fp16*)T2lo;

    dim3 tb(32, 8);

    // ---- fork ----
    zero_kernel<<<1, 64>>>(acc, 8);
    cudaEventRecord(eF, 0);
    cudaStreamWaitEvent(s1, eF, 0);
    cudaStreamWaitEvent(s2, eF, 0);
    cudaStreamWaitEvent(s3, eF, 0);

    // ======== stream s2: EN weight conversions, then beta EN ========
    tconv_f16hi<<<dim3(16, 938), tb, 0, s2>>>(W1_en, W1Eh, NV_EN, HD, KP_EN);
    cudaEventRecord(eW1E, s2);
    tconv<<<dim3(16, 16), tb, 0, s2>>>(W2_en, W2Ehi, W2Elo, HD, HD, 512);
    tconv<<<dim3(4, 16), tb, 0, s2>>>(Wmu_en, MVEhi, MVElo, HD, KT, 512);
    tconv<<<dim3(4, 16), tb, 0, s2>>>(Wlv_en, MVEhi + 100 * 512, MVElo + 100 * 512, HD, KT, 512);
    cudaEventRecord(eWsmE, s2);
    rownorm2_kernel<<<(NV_EN * 32 + 255) / 256, 256, 0, s2>>>(we_en, wn, NV_EN, DE);
    rownorm2_kernel<<<(KT * 32 + 255) / 256, 256, 0, s2>>>(topic, tnm, KT, DE);
    conv_f16split<<<256, 256, 0, s2>>>(topic, tEh, tEl, KT, DE, 320);
    conv_f16hi<<<4096, 256, 0, s2>>>(we_en, weEh, NV_EN, DE, 320);
    launch_tch<1>(weEh, tEh, tEl, G, NV_EN, KT, 320, 1, 0, s2);
    zero_kernel<<<1, 128, 0, s2>>>(cs, KT);
    beta_pass1<<<(NV_EN + 255) / 256, 256, 0, s2>>>(G, wn, tnm, beta_en_out, cs, NV_EN);
    beta_pass2<<<2048, 256, 0, s2>>>(beta_en_out, cs, NV_EN);
    tconv<<<dim3(938, 4), tb, 0, s2>>>(beta_en_out, BEhi, BElo, KT, NV_EN, 128);

    // ======== stream s3: CN weight conversions, then beta CN ========
    tconv_f16hi<<<dim3(16, 626), tb, 0, s3>>>(W1_cn, W1Ch, NV_CN, HD, KP_CN);
    cudaEventRecord(eW1C, s3);
    tconv<<<dim3(16, 16), tb, 0, s3>>>(W2_cn, W2Chi, W2Clo, HD, HD, 512);
    tconv<<<dim3(4, 16), tb, 0, s3>>>(Wmu_cn, MVChi, MVClo, HD, KT, 512);
    tconv<<<dim3(4, 16), tb, 0, s3>>>(Wlv_cn, MVChi + 100 * 512, MVClo + 100 * 512, HD, KT, 512);
    cudaEventRecord(eWsmC, s3);
    rownorm2_kernel<<<(NV_CN * 32 + 255) / 256, 256, 0, s3>>>(we_cn, wn2, NV_CN, DE);
    rownorm2_kernel<<<(KT * 32 + 255) / 256, 256, 0, s3>>>(topic, tnm2, KT, DE);
    conv_f16split<<<256, 256, 0, s3>>>(topic, tCh, tCl, KT, DE, 320);
    conv_f16hi<<<4096, 256, 0, s3>>>(we_cn, weCh, NV_CN, DE, 320);
    launch_tch<1>(weCh, tCh, tCl, G2, NV_CN, KT, 320, 1, 0, s3);
    zero_kernel<<<1, 128, 0, s3>>>(cs2, KT);
    beta_pass1<<<(NV_CN + 255) / 256, 256, 0, s3>>>(G2, wn2, tnm2, beta_cn_out, cs2, NV_CN);
    beta_pass2<<<2048, 256, 0, s3>>>(beta_cn_out, cs2, NV_CN);
    tconv<<<dim3(626, 4), tb, 0, s3>>>(beta_cn_out, BChi, BClo, KT, NV_CN, 128);

    // ======== stream 0: EN encoder ========
    zero_kernel<<<1024, 256>>>(h1, B_SZ * HD);
    zero_kernel<<<1024, 256>>>(h2, B_SZ * HD);
    zero_kernel<<<512, 256>>>(mulv, B_SZ * 200);
    conv_f16hi<<<4096, 256>>>(x_en, xEh, B_SZ, NV_EN, KP_EN);
    cudaStreamWaitEvent(0, eW1E, 0);
    launch_tch<0>(xEh, W1Eh, W1Eh, h1, B_SZ, HD, KP_EN, 16, 1, 0);
    bias_sp_conv<<<1024, 256>>>(h1, b1_en, Ahs, Alo, B_SZ, HD);
    cudaStreamWaitEvent(0, eWsmE, 0);
    launch_tc3<1>(Ahs, Alo, W2Ehi, W2Elo, h2, B_SZ, HD, 512, 8, 1, 0);
    bias_sp_conv<<<1024, 256>>>(h2, b2_en, Ahs, Alo, B_SZ, HD);
    launch_tc3<1>(Ahs, Alo, MVEhi, MVElo, mulv, B_SZ, 200, 512, 8, 1, 0);
    theta_kl_kernel<<<B_SZ, 128>>>(mulv, bmu_en, blv_en, eps_en, th_en, theta_en_out, thEhi, thElo, acc + 1);
    cudaEventRecord(eMt, 0);

    // ======== stream s1: CN encoder ========
    zero_kernel<<<1024, 256, 0, s1>>>(h1c, B_SZ * HD);
    zero_kernel<<<1024, 256, 0, s1>>>(h2c, B_SZ * HD);
    zero_kernel<<<512, 256, 0, s1>>>(mulvc, B_SZ * 200);
    conv_f16hi<<<4096, 256, 0, s1>>>(x_cn, xCh, B_SZ, NV_CN, KP_CN);
    cudaStreamWaitEvent(s1, eW1C, 0);
    launch_tch<0>(xCh, W1Ch, W1Ch, h1c, B_SZ, HD, KP_CN, 16, 1, s1);
    bias_sp_conv<<<1024, 256, 0, s1>>>(h1c, b1_cn, A2hs, A2lo, B_SZ, HD);
    cudaStreamWaitEvent(s1, eWsmC, 0);
    launch_tc3<1>(A2hs, A2lo, W2Chi, W2Clo, h2c, B_SZ, HD, 512, 8, 1, s1);
    bias_sp_conv<<<1024, 256, 0, s1>>>(h2c, b2_cn, A2hs, A2lo, B_SZ, HD);
    launch_tc3<1>(A2hs, A2lo, MVChi, MVClo, mulvc, B_SZ, 200, 512, 8, 1, s1);
    theta_kl_kernel<<<B_SZ, 128, 0, s1>>>(mulvc, bmu_cn, blv_cn, eps_cn, th_cn, theta_cn_out, thChi, thClo, acc + 3);
    cudaEventRecord(e1t, s1);

    // ======== recon tails ========
    cudaStreamWaitEvent(s2, eMt, 0);
    launch_tc3<0>(thEhi, thElo, BEhi, BElo, recon, B_SZ, NV_EN, 128, 1, 0, s2);
    recon_loss_kernel<<<B_SZ, 256, 0, s2>>>(x_en, recon, NV_EN, acc + 0);
    cudaEventRecord(e2e, s2);

    cudaStreamWaitEvent(s3, e1t, 0);
    launch_tc3<0>(thChi, thClo, BChi, BClo, recon2, B_SZ, NV_CN, 128, 1, 0, s3);
    recon_loss_kernel<<<B_SZ, 256, 0, s3>>>(x_cn, recon2, NV_CN, acc + 2);
    cudaEventRecord(e3e, s3);

    // ======== stream 0: alignment, contrastive, join ========
    norm_topic_kernel<<<KT, 128>>>(topic, tnT);
    cmat_kernel<<<KT, 128>>>(tnT, Cm);
    sinkhorn_kernel<<<1, 256>>>(Cm, acc);
    cudaStreamWaitEvent(0, e1t, 0);
    select_norm_kernel<<<B_SZ, 128>>>(th_en, th_cn, tnb);
    contrast_kernel<<<B_SZ, 256>>>(tnb, cid, acc);
    cudaStreamWaitEvent(0, e2e, 0);
    cudaStreamWaitEvent(0, e3e, 0);
    finalize_kernel<<<1, 1>>>(acc, out);
}

// round 17
// speedup vs baseline: 1.4413x; 1.0708x over previous
#include <cuda_runtime.h>
#include <cuda_bf16.h>
#include <cuda_fp16.h>
#include <math.h>
#include <stdint.h>

#define B_SZ 512
#define NV_EN 30000
#define NV_CN 20000
#define KT 100
#define HD 512
#define DE 300
#define TAU_ 1.0f
#define EPS_SK 0.1f

#define KP_EN 30016
#define KP_CN 20032
#define GR_EN 30080
#define GR_CN 20096

typedef __nv_bfloat16 bf16;
typedef __half fp16;

// ---------------- device scratch ----------------
__device__ __align__(16) bf16 g_Ahi[B_SZ * KP_EN];     // fp16 x_en
__device__ __align__(16) bf16 g_Bhi[B_SZ * KP_EN];     // fp16 W1_en hi
__device__ __align__(16) bf16 g_Alo[B_SZ * HD];
__device__ __align__(16) bf16 g_Ahs[B_SZ * HD];
__device__ __align__(16) bf16 g_A2hi[B_SZ * KP_CN];    // fp16 x_cn
__device__ __align__(16) bf16 g_B2hi[B_SZ * KP_CN];    // fp16 W1_cn hi
__device__ __align__(16) bf16 g_A2lo[B_SZ * HD];
__device__ __align__(16) bf16 g_A2hs[B_SZ * HD];
__device__ __align__(16) bf16 g_W2Ehi[512 * 512];
__device__ __align__(16) bf16 g_W2Elo[512 * 512];
__device__ __align__(16) bf16 g_MVEhi[256 * 512];
__device__ __align__(16) bf16 g_MVElo[256 * 512];
__device__ __align__(16) bf16 g_W2Chi[512 * 512];
__device__ __align__(16) bf16 g_W2Clo[512 * 512];
__device__ __align__(16) bf16 g_MVChi[256 * 512];
__device__ __align__(16) bf16 g_MVClo[256 * 512];
__device__ __align__(16) bf16 g_WEhi[GR_EN * 320];     // fp16 we_en
__device__ __align__(16) bf16 g_Thi [128 * 320];       // fp16 topic hi
__device__ __align__(16) bf16 g_Tlo [128 * 320];       // fp16 topic lo
__device__ __align__(16) bf16 g_BEhi[GR_EN * 128];
__device__ __align__(16) bf16 g_BElo[GR_EN * 128];
__device__ __align__(16) bf16 g_thEhi[B_SZ * 128];
__device__ __align__(16) bf16 g_thElo[B_SZ * 128];
__device__ __align__(16) bf16 g_WChi[GR_CN * 320];     // fp16 we_cn
__device__ __align__(16) bf16 g_T2hi[128 * 320];
__device__ __align__(16) bf16 g_T2lo[128 * 320];
__device__ __align__(16) bf16 g_BChi[GR_CN * 128];
__device__ __align__(16) bf16 g_BClo[GR_CN * 128];
__device__ __align__(16) bf16 g_thChi[B_SZ * 128];
__device__ __align__(16) bf16 g_thClo[B_SZ * 128];
__device__ __align__(16) float g_h1 [B_SZ * HD];
__device__ __align__(16) float g_h2 [B_SZ * HD];
__device__ __align__(16) float g_mulv [B_SZ * 200];
__device__ __align__(16) float g_h1c[B_SZ * HD];
__device__ __align__(16) float g_h2c[B_SZ * HD];
__device__ __align__(16) float g_mulvc[B_SZ * 200];
__device__ __align__(16) float g_G  [NV_EN * KT];
__device__ __align__(16) float g_G2 [NV_CN * KT];
__device__ __align__(16) float g_rlE[3 * B_SZ];   // S, D, X per row (EN)
__device__ __align__(16) float g_rlC[3 * B_SZ];   // S, D, X per row (CN)
__device__ __align__(16) float g_theta_en[B_SZ * KT];
__device__ __align__(16) float g_theta_cn[B_SZ * KT];
__device__ __align__(16) float g_wnorm [NV_EN];
__device__ __align__(16) float g_wnorm2[NV_CN];
__device__ __align__(16) float g_tnorm [KT];
__device__ __align__(16) float g_tnorm2[KT];
__device__ __align__(16) float g_tn[B_SZ * KT];
__device__ __align__(16) float g_tnT[KT * DE];
__device__ __align__(16) float g_C[KT * KT];
__device__ __align__(16) float g_cs [KT];
__device__ __align__(16) float g_cs2[KT];
__device__ __align__(16) float g_acc[8];

#define KC 32
#define AST 40

__device__ __forceinline__ void split2(float x, bf16& h, bf16& l) {
    h = __float2bfloat16(x);
    l = __float2bfloat16(x - __bfloat162float(h));
}
__device__ __forceinline__ void split2h(float x, fp16& h, fp16& l) {
    h = __float2half(x);
    l = __float2half(x - __half2float(h));
}

__device__ __forceinline__ void mma16816(float* c, const uint32_t* a, uint32_t b0, uint32_t b1) {
    asm volatile(
        "mma.sync.aligned.m16n8k16.row.col.f32.bf16.bf16.f32 "
        "{%0,%1,%2,%3}, {%4,%5,%6,%7}, {%8,%9}, {%0,%1,%2,%3};"
        : "+f"(c[0]), "+f"(c[1]), "+f"(c[2]), "+f"(c[3])
        : "r"(a[0]), "r"(a[1]), "r"(a[2]), "r"(a[3]), "r"(b0), "r"(b1));
}
__device__ __forceinline__ void mma16816h(float* c, const uint32_t* a, uint32_t b0, uint32_t b1) {
    asm volatile(
        "mma.sync.aligned.m16n8k16.row.col.f32.f16.f16.f32 "
        "{%0,%1,%2,%3}, {%4,%5,%6,%7}, {%8,%9}, {%0,%1,%2,%3};"
        : "+f"(c[0]), "+f"(c[1]), "+f"(c[2]), "+f"(c[3])
        : "r"(a[0]), "r"(a[1]), "r"(a[2]), "r"(a[3]), "r"(b0), "r"(b1));
}

// ======== split-bf16 GEMM (3 or 1 products) ========
template<int SPLIT>
__global__ __launch_bounds__(256)
void tc_gemm3(const bf16* __restrict__ Ahi, const bf16* __restrict__ Alo,
              const bf16* __restrict__ Bhi, const bf16* __restrict__ Blo,
              float* __restrict__ C, int M, int N, int Kp,
              int chunksPerZ, int mode)
{
    extern __shared__ __align__(16) bf16 smem[];
    const int TILE = 128 * AST;
    const int NT = SPLIT ? 4 : 2;
    const int STAGE = NT * TILE;

    int tid = threadIdx.x;
    int warp = tid >> 5, lane = tid & 31;
    int wm = warp >> 1, wn = warp & 1;
    int row0 = blockIdx.y * 128;
    int col0 = blockIdx.x * 128;
    int totalChunks = Kp / KC;
    int c0 = blockIdx.z * chunksPerZ;
    int nC = min(chunksPerZ, totalChunks - c0);
    if (nC <= 0) return;

    float acc[2][8][4];
#pragma unroll
    for (int i = 0; i < 2; i++)
#pragma unroll
        for (int j = 0; j < 8; j++)
#pragma unroll
            for (int q = 0; q < 4; q++) acc[i][j][q] = 0.f;

    int g = lane >> 2, t4 = lane & 3;

    auto issue_copy = [&](int s, int k0) {
#pragma unroll
        for (int it = 0; it < 2 * NT; it++) {
            const int t = it >> 1;
            int idx = ((it & 1) << 8) | tid;
            int r = idx >> 2, j = idx & 3;
            const bf16* src;
            int rb;
            if (SPLIT) {
                src = (t == 0) ? Ahi : (t == 1) ? Alo : (t == 2) ? Bhi : Blo;
                rb = (t < 2) ? row0 : col0;
            } else {
                src = (t == 0) ? Ahi : Bhi;
                rb = (t == 0) ? row0 : col0;
            }
            const bf16* gp = src + (size_t)(rb + r) * Kp + k0 + j * 8;
            bf16* dp = smem + s * STAGE + t * TILE + r * AST + j * 8;
            uint32_t da = (uint32_t)__cvta_generic_to_shared(dp);
            asm volatile("cp.async.cg.shared.global [%0], [%1], 16;" :: "r"(da), "l"(gp));
        }
        asm volatile("cp.async.commit_group;" ::: "memory");
    };

    issue_copy(0, c0 * KC);

    for (int lc = 0; lc < nC; lc++) {
        if (lc + 1 < nC) {
            issue_copy((lc + 1) & 1, (c0 + lc + 1) * KC);
            asm volatile("cp.async.wait_group 1;" ::: "memory");
        } else {
            asm volatile("cp.async.wait_group 0;" ::: "memory");
        }
        __syncthreads();

        const bf16* sAh = smem + (lc & 1) * STAGE;
        const bf16* sAl = sAh + TILE;
        const bf16* sBh = SPLIT ? (sAh + 2 * TILE) : (sAh + TILE);
        const bf16* sBl = sAh + 3 * TILE;

#pragma unroll
        for (int ks = 0; ks < 2; ks++) {
            int kb = ks * 16 + t4 * 2;
            uint32_t ah[2][4], al[2][4];
#pragma unroll
            for (int mf = 0; mf < 2; mf++) {
                int ar = wm * 32 + mf * 16 + g;
                int base = ar * AST + kb;
                ah[mf][0] = *reinterpret_cast<const uint32_t*>(&sAh[base]);
                ah[mf][1] = *reinterpret_cast<const uint32_t*>(&sAh[base + 8 * AST]);
                ah[mf][2] = *reinterpret_cast<const uint32_t*>(&sAh[base + 8]);
                ah[mf][3] = *reinterpret_cast<const uint32_t*>(&sAh[base + 8 * AST + 8]);
                if (SPLIT) {
                    al[mf][0] = *reinterpret_cast<const uint32_t*>(&sAl[base]);
                    al[mf][1] = *reinterpret_cast<const uint32_t*>(&sAl[base + 8 * AST]);
                    al[mf][2] = *reinterpret_cast<const uint32_t*>(&sAl[base + 8]);
                    al[mf][3] = *reinterpret_cast<const uint32_t*>(&sAl[base + 8 * AST + 8]);
                }
            }
#pragma unroll
            for (int nf = 0; nf < 8; nf++) {
                int bn = wn * 64 + nf * 8 + g;
                int bbase = bn * AST + kb;
                uint32_t bh0 = *reinterpret_cast<const uint32_t*>(&sBh[bbase]);
                uint32_t bh1 = *reinterpret_cast<const uint32_t*>(&sBh[bbase + 8]);
#pragma unroll
                for (int mf = 0; mf < 2; mf++)
                    mma16816(acc[mf][nf], ah[mf], bh0, bh1);
                if (SPLIT) {
                    uint32_t bl0 = *reinterpret_cast<const uint32_t*>(&sBl[bbase]);
                    uint32_t bl1 = *reinterpret_cast<const uint32_t*>(&sBl[bbase + 8]);
#pragma unroll
                    for (int mf = 0; mf < 2; mf++) {
                        mma16816(acc[mf][nf], ah[mf], bl0, bl1);
                        mma16816(acc[mf][nf], al[mf], bh0, bh1);
                    }
                }
            }
        }
        __syncthreads();
    }

#pragma unroll
    for (int mf = 0; mf < 2; mf++) {
#pragma unroll
        for (int nf = 0; nf < 8; nf++) {
            int r = row0 + wm * 32 + mf * 16 + g;
            int c = col0 + wn * 64 + nf * 8 + t4 * 2;
            float* a4 = acc[mf][nf];
#pragma unroll
            for (int h = 0; h < 2; h++) {
                int rr = r + h * 8;
                if (rr >= M) continue;
#pragma unroll
                for (int q = 0; q < 2; q++) {
                    int cc = c + q;
                    if (cc >= N) continue;
                    float v = a4[h * 2 + q];
                    if (mode) atomicAdd(&C[(size_t)rr * N + cc], v);
                    else C[(size_t)rr * N + cc] = v;
                }
            }
        }
    }
}

// ======== fp16 GEMM: C = Ah @ Bh^T (+ Ah @ Bl^T if SPLITB) ========
template<int SPLITB>
__global__ __launch_bounds__(256)
void tc_gemm_h(const fp16* __restrict__ A, const fp16* __restrict__ Bh,
               const fp16* __restrict__ Bl, float* __restrict__ C,
               int M, int N, int Kp, int chunksPerZ, int mode)
{
    extern __shared__ __align__(16) fp16 smemh[];
    const int TILE = 128 * AST;
    const int NT = 2 + SPLITB;
    const int STAGE = NT * TILE;

    int tid = threadIdx.x;
    int warp = tid >> 5, lane = tid & 31;
    int wm = warp >> 1, wn = warp & 1;
    int row0 = blockIdx.y * 128;
    int col0 = blockIdx.x * 128;
    int totalChunks = Kp / KC;
    int c0 = blockIdx.z * chunksPerZ;
    int nC = min(chunksPerZ, totalChunks - c0);
    if (nC <= 0) return;

    float acc[2][8][4];
#pragma unroll
    for (int i = 0; i < 2; i++)
#pragma unroll
        for (int j = 0; j < 8; j++)
#pragma unroll
            for (int q = 0; q < 4; q++) acc[i][j][q] = 0.f;

    int g = lane >> 2, t4 = lane & 3;

    auto issue_copy = [&](int s, int k0) {
#pragma unroll
        for (int it = 0; it < 2 * NT; it++) {
            const int t = it >> 1;
            int idx = ((it & 1) << 8) | tid;
            int r = idx >> 2, j = idx & 3;
            const fp16* src = (t == 0) ? A : (t == 1) ? Bh : Bl;
            int rb = (t == 0) ? row0 : col0;
            const fp16* gp = src + (size_t)(rb + r) * Kp + k0 + j * 8;
            fp16* dp = smemh + s * STAGE + t * TILE + r * AST + j * 8;
            uint32_t da = (uint32_t)__cvta_generic_to_shared(dp);
            asm volatile("cp.async.cg.shared.global [%0], [%1], 16;" :: "r"(da), "l"(gp));
        }
        asm volatile("cp.async.commit_group;" ::: "memory");
    };

    issue_copy(0, c0 * KC);

    for (int lc = 0; lc < nC; lc++) {
        if (lc + 1 < nC) {
            issue_copy((lc + 1) & 1, (c0 + lc + 1) * KC);
            asm volatile("cp.async.wait_group 1;" ::: "memory");
        } else {
            asm volatile("cp.async.wait_group 0;" ::: "memory");
        }
        __syncthreads();

        const fp16* sA  = smemh + (lc & 1) * STAGE;
        const fp16* sBh = sA + TILE;
        const fp16* sBl = sA + 2 * TILE;

#pragma unroll
        for (int ks = 0; ks < 2; ks++) {
            int kb = ks * 16 + t4 * 2;
            uint32_t ah[2][4];
#pragma unroll
            for (int mf = 0; mf < 2; mf++) {
                int ar = wm * 32 + mf * 16 + g;
                int base = ar * AST + kb;
                ah[mf][0] = *reinterpret_cast<const uint32_t*>(&sA[base]);
                ah[mf][1] = *reinterpret_cast<const uint32_t*>(&sA[base + 8 * AST]);
                ah[mf][2] = *reinterpret_cast<const uint32_t*>(&sA[base + 8]);
                ah[mf][3] = *reinterpret_cast<const uint32_t*>(&sA[base + 8 * AST + 8]);
            }
#pragma unroll
            for (int nf = 0; nf < 8; nf++) {
                int bn = wn * 64 + nf * 8 + g;
                int bbase = bn * AST + kb;
                uint32_t bh0 = *reinterpret_cast<const uint32_t*>(&sBh[bbase]);
                uint32_t bh1 = *reinterpret_cast<const uint32_t*>(&sBh[bbase + 8]);
#pragma unroll
                for (int mf = 0; mf < 2; mf++)
                    mma16816h(acc[mf][nf], ah[mf], bh0, bh1);
                if (SPLITB) {
                    uint32_t bl0 = *reinterpret_cast<const uint32_t*>(&sBl[bbase]);
                    uint32_t bl1 = *reinterpret_cast<const uint32_t*>(&sBl[bbase + 8]);
#pragma unroll
                    for (int mf = 0; mf < 2; mf++)
                        mma16816h(acc[mf][nf], ah[mf], bl0, bl1);
                }
            }
        }
        __syncthreads();
    }

#pragma unroll
    for (int mf = 0; mf < 2; mf++) {
#pragma unroll
        for (int nf = 0; nf < 8; nf++) {
            int r = row0 + wm * 32 + mf * 16 + g;
            int c = col0 + wn * 64 + nf * 8 + t4 * 2;
            float* a4 = acc[mf][nf];
#pragma unroll
            for (int h = 0; h < 2; h++) {
                int rr = r + h * 8;
                if (rr >= M) continue;
#pragma unroll
                for (int q = 0; q < 2; q++) {
                    int cc = c + q;
                    if (cc >= N) continue;
                    float v = a4[h * 2 + q];
                    if (mode) atomicAdd(&C[(size_t)rr * N + cc], v);
                    else C[(size_t)rr * N + cc] = v;
                }
            }
        }
    }
}

// ======== recon GEMM with FUSED loss epilogue ========
// r = theta @ beta^T; r in [0,1] provably (beta col-normalized, theta simplex)
// so logsumexp needs no max subtraction. Accumulates per-row:
//   S += exp(r), D += x*r, X += x   via width-4 shuffle + atomics.
__global__ __launch_bounds__(256)
void tc_recon(const bf16* __restrict__ Ahi, const bf16* __restrict__ Bhi,
              const float* __restrict__ x,
              float* __restrict__ S, float* __restrict__ D, float* __restrict__ X,
              int M, int N, int Kp, int chunksPerZ)
{
    extern __shared__ __align__(16) bf16 smem[];
    const int TILE = 128 * AST;
    const int STAGE = 2 * TILE;

    int tid = threadIdx.x;
    int warp = tid >> 5, lane = tid & 31;
    int wm = warp >> 1, wn = warp & 1;
    int row0 = blockIdx.y * 128;
    int col0 = blockIdx.x * 128;
    int totalChunks = Kp / KC;
    int nC = totalChunks;

    float acc[2][8][4];
#pragma unroll
    for (int i = 0; i < 2; i++)
#pragma unroll
        for (int j = 0; j < 8; j++)
#pragma unroll
            for (int q = 0; q < 4; q++) acc[i][j][q] = 0.f;

    int g = lane >> 2, t4 = lane & 3;

    auto issue_copy = [&](int s, int k0) {
#pragma unroll
        for (int it = 0; it < 4; it++) {
            const int t = it >> 1;
            int idx = ((it & 1) << 8) | tid;
            int r = idx >> 2, j = idx & 3;
            const bf16* src = (t == 0) ? Ahi : Bhi;
            int rb = (t == 0) ? row0 : col0;
            const bf16* gp = src + (size_t)(rb + r) * Kp + k0 + j * 8;
            bf16* dp = smem + s * STAGE + t * TILE + r * AST + j * 8;
            uint32_t da = (uint32_t)__cvta_generic_to_shared(dp);
            asm volatile("cp.async.cg.shared.global [%0], [%1], 16;" :: "r"(da), "l"(gp));
        }
        asm volatile("cp.async.commit_group;" ::: "memory");
    };

    issue_copy(0, 0);

    for (int lc = 0; lc < nC; lc++) {
        if (lc + 1 < nC) {
            issue_copy((lc + 1) & 1, (lc + 1) * KC);
            asm volatile("cp.async.wait_group 1;" ::: "memory");
        } else {
            asm volatile("cp.async.wait_group 0;" ::: "memory");
        }
        __syncthreads();

        const bf16* sAh = smem + (lc & 1) * STAGE;
        const bf16* sBh = sAh + TILE;

#pragma unroll
        for (int ks = 0; ks < 2; ks++) {
            int kb = ks * 16 + t4 * 2;
            uint32_t ah[2][4];
#pragma unroll
            for (int mf = 0; mf < 2; mf++) {
                int ar = wm * 32 + mf * 16 + g;
                int base = ar * AST + kb;
                ah[mf][0] = *reinterpret_cast<const uint32_t*>(&sAh[base]);
                ah[mf][1] = *reinterpret_cast<const uint32_t*>(&sAh[base + 8 * AST]);
                ah[mf][2] = *reinterpret_cast<const uint32_t*>(&sAh[base + 8]);
                ah[mf][3] = *reinterpret_cast<const uint32_t*>(&sAh[base + 8 * AST + 8]);
            }
#pragma unroll
            for (int nf = 0; nf < 8; nf++) {
                int bn = wn * 64 + nf * 8 + g;
                int bbase = bn * AST + kb;
                uint32_t bh0 = *reinterpret_cast<const uint32_t*>(&sBh[bbase]);
                uint32_t bh1 = *reinterpret_cast<const uint32_t*>(&sBh[bbase + 8]);
#pragma unroll
                for (int mf = 0; mf < 2; mf++)
                    mma16816(acc[mf][nf], ah[mf], bh0, bh1);
            }
        }
        __syncthreads();
    }

    // ---- fused loss epilogue ----
#pragma unroll
    for (int mf = 0; mf < 2; mf++) {
#pragma unroll
        for (int h = 0; h < 2; h++) {
            int rr = row0 + wm * 32 + mf * 16 + g + h * 8;
            float ps = 0.f, pd = 0.f, px = 0.f;
            if (rr < M) {
#pragma unroll
                for (int nf = 0; nf < 8; nf++) {
#pragma unroll
                    for (int q = 0; q < 2; q++) {
                        int cc = col0 + wn * 64 + nf * 8 + t4 * 2 + q;
                        if (cc < N) {
                            float r = acc[mf][nf][h * 2 + q];
                            float xv = x[(size_t)rr * N + cc];
                            ps += expf(r);
                            pd = fmaf(xv, r, pd);
                            px += xv;
                        }
                    }
                }
            }
            ps += __shfl_down_sync(0xffffffffu, ps, 2, 4);
            ps += __shfl_down_sync(0xffffffffu, ps, 1, 4);
            pd += __shfl_down_sync(0xffffffffu, pd, 2, 4);
            pd += __shfl_down_sync(0xffffffffu, pd, 1, 4);
            px += __shfl_down_sync(0xffffffffu, px, 2, 4);
            px += __shfl_down_sync(0xffffffffu, px, 1, 4);
            if (t4 == 0 && rr < M) {
                atomicAdd(&S[rr], ps);
                atomicAdd(&D[rr], pd);
                atomicAdd(&X[rr], px);
            }
        }
    }
}

// sum over rows: -D + X*log(S) -> acc
__global__ void recon_final(const float* __restrict__ rl, float* acc) {
    __shared__ float red[512];
    int i = threadIdx.x;
    float per = -rl[B_SZ + i] + rl[2 * B_SZ + i] * logf(rl[i]);
    red[i] = per;
    __syncthreads();
    for (int o = 256; o; o >>= 1) { if (i < o) red[i] += red[i + o]; __syncthreads(); }
    if (i == 0) atomicAdd(acc, red[0]);
}

// ---------------- conversions ----------------
__global__ void conv_f16hi(const float* __restrict__ src, fp16* __restrict__ hi,
                           int R, int K, int Kp) {
    size_t total = (size_t)R * Kp;
    for (size_t idx = blockIdx.x * (size_t)blockDim.x + threadIdx.x; idx < total;
         idx += (size_t)gridDim.x * blockDim.x) {
        int r = (int)(idx / Kp), k = (int)(idx % Kp);
        hi[idx] = __float2half((k < K) ? src[(size_t)r * K + k] : 0.f);
    }
}

__global__ void conv_f16split(const float* __restrict__ src, fp16* __restrict__ hi,
                              fp16* __restrict__ lo, int R, int K, int Kp) {
    size_t total = (size_t)R * Kp;
    for (size_t idx = blockIdx.x * (size_t)blockDim.x + threadIdx.x; idx < total;
         idx += (size_t)gridDim.x * blockDim.x) {
        int r = (int)(idx / Kp), k = (int)(idx % Kp);
        float v = (k < K) ? src[(size_t)r * K + k] : 0.f;
        fp16 h, l; split2h(v, h, l);
        hi[idx] = h; lo[idx] = l;
    }
}

__global__ void tconv(const float* __restrict__ src, bf16* __restrict__ hi, bf16* __restrict__ lo,
                      int R, int C, int Kp) {
    __shared__ float t[32][33];
    int kb = blockIdx.y * 32, nb = blockIdx.x * 32;
    int tx = threadIdx.x, ty = threadIdx.y;
#pragma unroll
    for (int i = 0; i < 4; i++) {
        int r = kb + ty + i * 8, c = nb + tx;
        t[ty + i * 8][tx] = (r < R && c < C) ? src[(size_t)r * C + c] : 0.f;
    }
    __syncthreads();
#pragma unroll
    for (int i = 0; i < 4; i++) {
        int n = nb + ty + i * 8, k = kb + tx;
        if (n < C && k < Kp) {
            bf16 h, l; split2(t[tx][ty + i * 8], h, l);
            hi[(size_t)n * Kp + k] = h;
            lo[(size_t)n * Kp + k] = l;
        }
    }
}

// bf16 hi-only transpose convert (for beta)
__global__ void tconv_hi(const float* __restrict__ src, bf16* __restrict__ hi,
                         int R, int C, int Kp) {
    __shared__ float t[32][33];
    int kb = blockIdx.y * 32, nb = blockIdx.x * 32;
    int tx = threadIdx.x, ty = threadIdx.y;
#pragma unroll
    for (int i = 0; i < 4; i++) {
        int r = kb + ty + i * 8, c = nb + tx;
        t[ty + i * 8][tx] = (r < R && c < C) ? src[(size_t)r * C + c] : 0.f;
    }
    __syncthreads();
#pragma unroll
    for (int i = 0; i < 4; i++) {
        int n = nb + ty + i * 8, k = kb + tx;
        if (n < C && k < Kp)
            hi[(size_t)n * Kp + k] = __float2bfloat16(t[tx][ty + i * 8]);
    }
}

__global__ void tconv_f16hi(const float* __restrict__ src, fp16* __restrict__ hi,
                            int R, int C, int Kp) {
    __shared__ float t[32][33];
    int kb = blockIdx.y * 32, nb = blockIdx.x * 32;
    int tx = threadIdx.x, ty = threadIdx.y;
#pragma unroll
    for (int i = 0; i < 4; i++) {
        int r = kb + ty + i * 8, c = nb + tx;
        t[ty + i * 8][tx] = (r < R && c < C) ? src[(size_t)r * C + c] : 0.f;
    }
    __syncthreads();
#pragma unroll
    for (int i = 0; i < 4; i++) {
        int n = nb + ty + i * 8, k = kb + tx;
        if (n < C && k < Kp)
            hi[(size_t)n * Kp + k] = __float2half(t[tx][ty + i * 8]);
    }
}

__global__ void bias_sp_conv(const float* __restrict__ X, const float* __restrict__ bias,
                             bf16* __restrict__ hi, bf16* __restrict__ lo, int M, int N) {
    int total = M * N;
    for (int idx = blockIdx.x * blockDim.x + threadIdx.x; idx < total; idx += gridDim.x * blockDim.x) {
        int j = idx % N;
        float v = X[idx] + bias[j];
        float sp = fmaxf(v, 0.f) + log1pf(expf(-fabsf(v)));
        bf16 h, l; split2(sp, h, l);
        hi[idx] = h; lo[idx] = l;
    }
}

// ---------------- elementwise / reductions ----------------
__global__ void zero_kernel(float* p, int n) {
    for (int i = blockIdx.x * blockDim.x + threadIdx.x; i < n; i += gridDim.x * blockDim.x)
        p[i] = 0.f;
}

__global__ void theta_kl_kernel(const float* __restrict__ mulv,
                                const float* __restrict__ bmu, const float* __restrict__ blv,
                                const float* __restrict__ eps, float* __restrict__ theta_scratch,
                                float* __restrict__ theta_dout,
                                bf16* __restrict__ thi, bf16* __restrict__ tlo, float* kl_acc)
{
    int i = blockIdx.x;
    int k = threadIdx.x;
    __shared__ float red[128];
    float zv = -1e30f, kl = 0.f;
    if (k < KT) {
        float mu = mulv[i * 200 + k] + bmu[k];
        float lv = mulv[i * 200 + 100 + k] + blv[k];
        zv = mu + eps[i * KT + k] * expf(0.5f * lv);
        kl = expf(lv) + mu * mu - 1.f - lv;
    }
    red[k] = zv; __syncthreads();
    for (int s = 64; s > 0; s >>= 1) { if (k < s) red[k] = fmaxf(red[k], red[k + s]); __syncthreads(); }
    float m = red[0]; __syncthreads();
    float e = (k < KT) ? expf(zv - m) : 0.f;
    red[k] = e; __syncthreads();
    for (int s = 64; s > 0; s >>= 1) { if (k < s) red[k] += red[k + s]; __syncthreads(); }
    float ssum = red[0]; __syncthreads();
    {
        float t = (k < KT) ? (e / ssum) : 0.f;
        if (k < KT) {
            theta_scratch[i * KT + k] = t;
            theta_dout[i * KT + k] = t;
        }
        bf16 h, l; split2(t, h, l);
        thi[i * 128 + k] = h;
        tlo[i * 128 + k] = l;
    }
    red[k] = (k < KT) ? kl : 0.f; __syncthreads();
    for (int s = 64; s > 0; s >>= 1) { if (k < s) red[k] += red[k + s]; __syncthreads(); }
    if (k == 0) atomicAdd(kl_acc, 0.5f * red[0]);
}

__global__ void rownorm2_kernel(const float* __restrict__ X, float* __restrict__ out, int R, int D) {
    int warp = (blockIdx.x * blockDim.x + threadIdx.x) >> 5;
    int lane = threadIdx.x & 31;
    if (warp >= R) return;
    float s = 0.f;
    for (int d = lane; d < D; d += 32) { float v = X[(size_t)warp * D + d]; s = fmaf(v, v, s); }
    for (int o = 16; o; o >>= 1) s += __shfl_down_sync(0xffffffffu, s, o);
    if (lane == 0) out[warp] = s;
}

__global__ void beta_pass1(const float* __restrict__ G, const float* __restrict__ wnorm,
                           const float* __restrict__ tnorm, float* __restrict__ beta_dout,
                           float* __restrict__ colsum, int V)
{
    __shared__ float tn_s[KT];
    __shared__ float wsum[8];
    int v = blockIdx.x * 256 + threadIdx.x;
    if (threadIdx.x < KT) tn_s[threadIdx.x] = tnorm[threadIdx.x];
    __syncthreads();
    bool ok = v < V;
    float wn = ok ? wnorm[v] : 0.f;
    int lane = threadIdx.x & 31, wid = threadIdx.x >> 5;
    for (int k = 0; k < KT; k++) {
        float e = 0.f;
        if (ok) {
            float sq = wn + tn_s[k] - 2.f * G[(size_t)v * KT + k];
            float d = sqrtf(fmaxf(sq, 0.f));
            e = expf(-d / TAU_);
            beta_dout[(size_t)k * V + v] = e;
        }
        float s = e;
        for (int o = 16; o; o >>= 1) s += __shfl_down_sync(0xffffffffu, s, o);
        if (lane == 0) wsum[wid] = s;
        __syncthreads();
        if (threadIdx.x == 0) {
            float t = 0.f;
            for (int w = 0; w < 8; w++) t += wsum[w];
            atomicAdd(&colsum[k], t);
        }
        __syncthreads();
    }
}

__global__ void beta_pass2(float* __restrict__ beta_dout, const float* __restrict__ colsum, int V) {
    int total = KT * V;
    for (int idx = blockIdx.x * blockDim.x + threadIdx.x; idx < total; idx += gridDim.x * blockDim.x) {
        int k = idx / V;
        beta_dout[idx] = beta_dout[idx] / colsum[k];
    }
}

__global__ void select_norm_kernel(const float* __restrict__ theta_en,
                                   const float* __restrict__ theta_cn, float* __restrict__ tn)
{
    int i = blockIdx.x;
    int k = threadIdx.x;
    __shared__ float red[128];
    const float* src = ((i & 1) == 0) ? theta_en : theta_cn;
    float v = (k < KT) ? src[i * KT + k] : 0.f;
    red[k] = v * v; __syncthreads();
    for (int s = 64; s > 0; s >>= 1) { if (k < s) red[k] += red[k + s]; __syncthreads(); }
    float nrm = fmaxf(sqrtf(red[0]), 1e-8f);
    if (k < KT) tn[i * KT + k] = v / nrm;
}

__global__ void contrast_kernel(const float* __restrict__ tn, const int* __restrict__ cid, float* acc)
{
    int i = blockIdx.x;
    int tid = threadIdx.x;
    __shared__ float ti[KT];
    if (tid < KT) ti[tid] = tn[i * KT + tid];
    __syncthreads();
    int ci = cid[i];
    bool vi = ci > 0;
    float pos = 0.f, neg = 0.f, pcnt = 0.f;
    for (int j = tid; j < B_SZ; j += 256) {
        if (j == i) continue;
        float s = 0.f;
        const float* tj = &tn[j * KT];
#pragma unroll 4
        for (int k = 0; k < KT; k++) s = fmaf(ti[k], tj[k], s);
        float E = expf(s / TAU_);
        neg += E;
        int cj = cid[j];
        if (vi && cj > 0 && cj == ci) { pos += E; pcnt += 1.f; }
    }
    __shared__ float r1[256], r2[256], r3[256];
    r1[tid] = pos; r2[tid] = neg; r3[tid] = pcnt;
    __syncthreads();
    for (int o = 128; o; o >>= 1) {
        if (tid < o) { r1[tid] += r1[tid + o]; r2[tid] += r2[tid + o]; r3[tid] += r3[tid + o]; }
        __syncthreads();
    }
    if (tid == 0) {
        if (vi && r3[0] > 0.5f) {
            float per = -logf(r1[0] / (r1[0] + r2[0] + 1e-8f));
            atomicAdd(&acc[4], per);
            atomicAdd(&acc[5], 1.f);
        }
    }
}

__global__ void norm_topic_kernel(const float* __restrict__ T, float* __restrict__ Tn) {
    int k = blockIdx.x;
    int d = threadIdx.x;
    __shared__ float red[128];
    float s = 0.f;
    for (int dd = d; dd < DE; dd += 128) { float v = T[k * DE + dd]; s = fmaf(v, v, s); }
    red[d] = s; __syncthreads();
    for (int o = 64; o > 0; o >>= 1) { if (d < o) red[d] += red[d + o]; __syncthreads(); }
    float nrm = fmaxf(sqrtf(red[0]), 1e-8f);
    for (int dd = d; dd < DE; dd += 128) Tn[k * DE + dd] = T[k * DE + dd] / nrm;
}

__global__ void cmat_kernel(const float* __restrict__ Tn, float* __restrict__ C) {
    int i = blockIdx.x;
    __shared__ float ti[DE];
    for (int d = threadIdx.x; d < DE; d += 128) ti[d] = Tn[i * DE + d];
    __syncthreads();
    for (int j = threadIdx.x; j < KT; j += 128) {
        float s = 0.f;
        for (int d = 0; d < DE; d++) s = fmaf(ti[d], Tn[j * DE + d], s);
        C[i * KT + j] = 1.f - s;
    }
}

__global__ void sinkhorn_kernel(const float* __restrict__ C, float* acc) {
    __shared__ float Ks[KT * KT];
    __shared__ float u[KT], v[KT];
    __shared__ float red[256];
    int tid = threadIdx.x;
    for (int idx = tid; idx < KT * KT; idx += 256) Ks[idx] = expf(-C[idx] / EPS_SK);
    if (tid < KT) { u[tid] = 1.f; v[tid] = 1.f; }
    __syncthreads();
    const float a = 1.f / KT;
    for (int it = 0; it < 50; it++) {
        if (tid < KT) {
            float d = 1e-8f;
            for (int j = 0; j < KT; j++) d = fmaf(Ks[tid * KT + j], v[j], d);
            u[tid] = a / d;
        }
        __syncthreads();
        if (tid < KT) {
            float d = 1e-8f;
            for (int i2 = 0; i2 < KT; i2++) d = fmaf(Ks[i2 * KT + tid], u[i2], d);
            v[tid] = a / d;
        }
        __syncthreads();
    }
    float s = 0.f;
    for (int idx = tid; idx < KT * KT; idx += 256) {
        int i2 = idx / KT, j = idx % KT;
        s += u[i2] * Ks[idx] * v[j] * C[idx];
    }
    red[tid] = s; __syncthreads();
    for (int o = 128; o; o >>= 1) { if (tid < o) red[tid] += red[tid + o]; __syncthreads(); }
    if (tid == 0) acc[6] = red[0];
}

__global__ void finalize_kernel(const float* __restrict__ acc, float* __restrict__ out) {
    float tm_en = acc[0] / (float)B_SZ + acc[1] / (float)B_SZ;
    float tm_cn = acc[2] / (float)B_SZ + acc[3] / (float)B_SZ;
    float contrast = acc[4] / (acc[5] + 1e-8f);
    float align = acc[6];
    out[0] = tm_en + tm_cn + contrast + align;
    out[1] = tm_en;
    out[2] = tm_cn;
    out[3] = contrast;
    out[4] = align;
}

// ---------------- host ----------------
template<int SPLIT>
static inline void launch_tc3(const bf16* Ah, const bf16* Al, const bf16* Bh, const bf16* Bl,
                              float* C, int M, int N, int Kp, int z, int mode, cudaStream_t st)
{
    size_t sm = (size_t)(SPLIT ? 4 : 2) * 2 * 128 * AST * sizeof(bf16);
    cudaFuncSetAttribute(tc_gemm3<SPLIT>, cudaFuncAttributeMaxDynamicSharedMemorySize, 98304);
    int total = Kp / KC;
    int per = (total + z - 1) / z;
    dim3 g((N + 127) / 128, (M + 127) / 128, z);
    tc_gemm3<SPLIT><<<g, 256, sm, st>>>(Ah, Al, Bh, Bl, C, M, N, Kp, per, mode);
}

template<int SPLITB>
static inline void launch_tch(const fp16* A, const fp16* Bh, const fp16* Bl,
                              float* C, int M, int N, int Kp, int z, int mode, cudaStream_t st)
{
    size_t sm = (size_t)(2 + SPLITB) * 2 * 128 * AST * sizeof(fp16);
    cudaFuncSetAttribute(tc_gemm_h<SPLITB>, cudaFuncAttributeMaxDynamicSharedMemorySize, 98304);
    int total = Kp / KC;
    int per = (total + z - 1) / z;
    dim3 g((N + 127) / 128, (M + 127) / 128, z);
    tc_gemm_h<SPLITB><<<g, 256, sm, st>>>(A, Bh, Bl, C, M, N, Kp, per, mode);
}

static inline void launch_recon(const bf16* Ah, const bf16* Bh, const float* x,
                                float* rl, int M, int N, int Kp, cudaStream_t st)
{
    size_t sm = (size_t)2 * 2 * 128 * AST * sizeof(bf16);
    cudaFuncSetAttribute(tc_recon, cudaFuncAttributeMaxDynamicSharedMemorySize, 98304);
    dim3 g((N + 127) / 128, (M + 127) / 128, 1);
    tc_recon<<<g, 256, sm, st>>>(Ah, Bh, x, rl, rl + B_SZ, rl + 2 * B_SZ, M, N, Kp, Kp / KC);
}

extern "C" void kernel_launch(void* const* d_in, const int* in_sizes, int n_in,
                              void* d_out, int out_size)
{
    const float* x_en   = (const float*)d_in[0];
    const float* x_cn   = (const float*)d_in[1];
    const int*   cid    = (const int*)  d_in[2];
    const float* eps_en = (const float*)d_in[3];
    const float* eps_cn = (const float*)d_in[4];
    const float* W1_en  = (const float*)d_in[5];
    const float* b1_en  = (const float*)d_in[6];
    const float* W2_en  = (const float*)d_in[7];
    const float* b2_en  = (const float*)d_in[8];
    const float* Wmu_en = (const float*)d_in[9];
    const float* bmu_en = (const float*)d_in[10];
    const float* Wlv_en = (const float*)d_in[11];
    const float* blv_en = (const float*)d_in[12];
    const float* W1_cn  = (const float*)d_in[13];
    const float* b1_cn  = (const float*)d_in[14];
    const float* W2_cn  = (const float*)d_in[15];
    const float* b2_cn  = (const float*)d_in[16];
    const float* Wmu_cn = (const float*)d_in[17];
    const float* bmu_cn = (const float*)d_in[18];
    const float* Wlv_cn = (const float*)d_in[19];
    const float* blv_cn = (const float*)d_in[20];
    const float* we_en  = (const float*)d_in[21];
    const float* we_cn  = (const float*)d_in[22];
    const float* topic  = (const float*)d_in[23];

    float* out = (float*)d_out;
    float* theta_en_out = out + 5;
    float* theta_cn_out = theta_en_out + B_SZ * KT;
    float* beta_en_out  = theta_cn_out + B_SZ * KT;
    float* beta_cn_out  = beta_en_out + KT * NV_EN;

    static cudaStream_t s1 = nullptr, s2 = nullptr, s3 = nullptr;
    static cudaEvent_t eF, eMt, e1t, e2e, e3e, eW1E, eWsmE, eW1C, eWsmC;
    if (!s1) {
        cudaStreamCreateWithFlags(&s1, cudaStreamNonBlocking);
        cudaStreamCreateWithFlags(&s2, cudaStreamNonBlocking);
        cudaStreamCreateWithFlags(&s3, cudaStreamNonBlocking);
        cudaEventCreateWithFlags(&eF,   cudaEventDisableTiming);
        cudaEventCreateWithFlags(&eMt,  cudaEventDisableTiming);
        cudaEventCreateWithFlags(&e1t,  cudaEventDisableTiming);
        cudaEventCreateWithFlags(&e2e,  cudaEventDisableTiming);
        cudaEventCreateWithFlags(&e3e,  cudaEventDisableTiming);
        cudaEventCreateWithFlags(&eW1E, cudaEventDisableTiming);
        cudaEventCreateWithFlags(&eWsmE, cudaEventDisableTiming);
        cudaEventCreateWithFlags(&eW1C, cudaEventDisableTiming);
        cudaEventCreateWithFlags(&eWsmC, cudaEventDisableTiming);
    }

    float *h1, *h2, *mulv, *h1c, *h2c, *mulvc, *G, *G2, *rlE, *rlC,
          *th_en, *th_cn, *wn, *wn2, *tnm, *tnm2, *tnb, *tnT, *Cm, *cs, *cs2, *acc;
    bf16 *Ahi, *Bhi, *Ahs, *Alo, *A2hi, *B2hi, *A2hs, *A2lo,
         *W2Ehi, *W2Elo, *MVEhi, *MVElo, *W2Chi, *W2Clo, *MVChi, *MVClo,
         *WEhi, *Thi, *Tlo, *BEhi, *thEhi, *thElo,
         *WChi, *T2hi, *T2lo, *BChi, *thChi, *thClo;
    cudaGetSymbolAddress((void**)&Ahi,   g_Ahi);
    cudaGetSymbolAddress((void**)&Bhi,   g_Bhi);
    cudaGetSymbolAddress((void**)&Ahs,   g_Ahs);   cudaGetSymbolAddress((void**)&Alo,   g_Alo);
    cudaGetSymbolAddress((void**)&A2hi,  g_A2hi);
    cudaGetSymbolAddress((void**)&B2hi,  g_B2hi);
    cudaGetSymbolAddress((void**)&A2hs,  g_A2hs);  cudaGetSymbolAddress((void**)&A2lo,  g_A2lo);
    cudaGetSymbolAddress((void**)&W2Ehi, g_W2Ehi); cudaGetSymbolAddress((void**)&W2Elo, g_W2Elo);
    cudaGetSymbolAddress((void**)&MVEhi, g_MVEhi); cudaGetSymbolAddress((void**)&MVElo, g_MVElo);
    cudaGetSymbolAddress((void**)&W2Chi, g_W2Chi); cudaGetSymbolAddress((void**)&W2Clo, g_W2Clo);
    cudaGetSymbolAddress((void**)&MVChi, g_MVChi); cudaGetSymbolAddress((void**)&MVClo, g_MVClo);
    cudaGetSymbolAddress((void**)&WEhi,  g_WEhi);
    cudaGetSymbolAddress((void**)&Thi,   g_Thi);   cudaGetSymbolAddress((void**)&Tlo,   g_Tlo);
    cudaGetSymbolAddress((void**)&BEhi,  g_BEhi);
    cudaGetSymbolAddress((void**)&thEhi, g_thEhi); cudaGetSymbolAddress((void**)&thElo, g_thElo);
    cudaGetSymbolAddress((void**)&WChi,  g_WChi);
    cudaGetSymbolAddress((void**)&T2hi,  g_T2hi);  cudaGetSymbolAddress((void**)&T2lo,  g_T2lo);
    cudaGetSymbolAddress((void**)&BChi,  g_BChi);
    cudaGetSymbolAddress((void**)&thChi, g_thChi); cudaGetSymbolAddress((void**)&thClo, g_thClo);
    cudaGetSymbolAddress((void**)&h1,    g_h1);    cudaGetSymbolAddress((void**)&h2,    g_h2);
    cudaGetSymbolAddress((void**)&mulv,  g_mulv);
    cudaGetSymbolAddress((void**)&h1c,   g_h1c);   cudaGetSymbolAddress((void**)&h2c,   g_h2c);
    cudaGetSymbolAddress((void**)&mulvc, g_mulvc);
    cudaGetSymbolAddress((void**)&G,     g_G);     cudaGetSymbolAddress((void**)&G2,    g_G2);
    cudaGetSymbolAddress((void**)&rlE,   g_rlE);   cudaGetSymbolAddress((void**)&rlC,   g_rlC);
    cudaGetSymbolAddress((void**)&th_en, g_theta_en);
    cudaGetSymbolAddress((void**)&th_cn, g_theta_cn);
    cudaGetSymbolAddress((void**)&wn,    g_wnorm); cudaGetSymbolAddress((void**)&wn2,   g_wnorm2);
    cudaGetSymbolAddress((void**)&tnm,   g_tnorm); cudaGetSymbolAddress((void**)&tnm2,  g_tnorm2);
    cudaGetSymbolAddress((void**)&tnb,   g_tn);
    cudaGetSymbolAddress((void**)&tnT,   g_tnT);
    cudaGetSymbolAddress((void**)&Cm,    g_C);
    cudaGetSymbolAddress((void**)&cs,    g_cs);    cudaGetSymbolAddress((void**)&cs2,   g_cs2);
    cudaGetSymbolAddress((void**)&acc,   g_acc);

    fp16* xEh  = (fp16*)Ahi;   fp16* W1Eh = (fp16*)Bhi;
    fp16* xCh  = (fp16*)A2hi;  fp16* W1Ch = (fp16*)B2hi;
    fp16* weEh = (fp16*)WEhi;  fp16* tEh  = (fp16*)Thi;  fp16* tEl  = (fp16*)Tlo;
    fp16* weCh = (fp16*)WChi;  fp16* tCh  = (fp16*)T2hi; fp16* tCl  = (fp16*)T2lo;

    dim3 tb(32, 8);

    // ---- fork ----
    zero_kernel<<<1, 64>>>(acc, 8);
    cudaEventRecord(eF, 0);
    cudaStreamWaitEvent(s1, eF, 0);
    cudaStreamWaitEvent(s2, eF, 0);
    cudaStreamWaitEvent(s3, eF, 0);

    // ======== stream s2: EN weight conversions, then beta EN ========
    tconv_f16hi<<<dim3(16, 938), tb, 0, s2>>>(W1_en, W1Eh, NV_EN, HD, KP_EN);
    cudaEventRecord(eW1E, s2);
    tconv<<<dim3(16, 16), tb, 0, s2>>>(W2_en, W2Ehi, W2Elo, HD, HD, 512);
    tconv<<<dim3(4, 16), tb, 0, s2>>>(Wmu_en, MVEhi, MVElo, HD, KT, 512);
    tconv<<<dim3(4, 16), tb, 0, s2>>>(Wlv_en, MVEhi + 100 * 512, MVElo + 100 * 512, HD, KT, 512);
    cudaEventRecord(eWsmE, s2);
    rownorm2_kernel<<<(NV_EN * 32 + 255) / 256, 256, 0, s2>>>(we_en, wn, NV_EN, DE);
    rownorm2_kernel<<<(KT * 32 + 255) / 256, 256, 0, s2>>>(topic, tnm, KT, DE);
    conv_f16split<<<256, 256, 0, s2>>>(topic, tEh, tEl, KT, DE, 320);
    conv_f16hi<<<4096, 256, 0, s2>>>(we_en, weEh, NV_EN, DE, 320);
    launch_tch<1>(weEh, tEh, tEl, G, NV_EN, KT, 320, 1, 0, s2);
    zero_kernel<<<1, 128, 0, s2>>>(cs, KT);
    beta_pass1<<<(NV_EN + 255) / 256, 256, 0, s2>>>(G, wn, tnm, beta_en_out, cs, NV_EN);
    beta_pass2<<<2048, 256, 0, s2>>>(beta_en_out, cs, NV_EN);
    tconv_hi<<<dim3(938, 4), tb, 0, s2>>>(beta_en_out, BEhi, KT, NV_EN, 128);
    zero_kernel<<<2, 256, 0, s2>>>(rlE, 3 * B_SZ);

    // ======== stream s3: CN weight conversions, then beta CN ========
    tconv_f16hi<<<dim3(16, 626), tb, 0, s3>>>(W1_cn, W1Ch, NV_CN, HD, KP_CN);
    cudaEventRecord(eW1C, s3);
    tconv<<<dim3(16, 16), tb, 0, s3>>>(W2_cn, W2Chi, W2Clo, HD, HD, 512);
    tconv<<<dim3(4, 16), tb, 0, s3>>>(Wmu_cn, MVChi, MVClo, HD, KT, 512);
    tconv<<<dim3(4, 16), tb, 0, s3>>>(Wlv_cn, MVChi + 100 * 512, MVClo + 100 * 512, HD, KT, 512);
    cudaEventRecord(eWsmC, s3);
    rownorm2_kernel<<<(NV_CN * 32 + 255) / 256, 256, 0, s3>>>(we_cn, wn2, NV_CN, DE);
    rownorm2_kernel<<<(KT * 32 + 255) / 256, 256, 0, s3>>>(topic, tnm2, KT, DE);
    conv_f16split<<<256, 256, 0, s3>>>(topic, tCh, tCl, KT, DE, 320);
    conv_f16hi<<<4096, 256, 0, s3>>>(we_cn, weCh, NV_CN, DE, 320);
    launch_tch<1>(weCh, tCh, tCl, G2, NV_CN, KT, 320, 1, 0, s3);
    zero_kernel<<<1, 128, 0, s3>>>(cs2, KT);
    beta_pass1<<<(NV_CN + 255) / 256, 256, 0, s3>>>(G2, wn2, tnm2, beta_cn_out, cs2, NV_CN);
    beta_pass2<<<2048, 256, 0, s3>>>(beta_cn_out, cs2, NV_CN);
    tconv_hi<<<dim3(626, 4), tb, 0, s3>>>(beta_cn_out, BChi, KT, NV_CN, 128);
    zero_kernel<<<2, 256, 0, s3>>>(rlC, 3 * B_SZ);

    // ======== stream 0: EN encoder ========
    zero_kernel<<<1024, 256>>>(h1, B_SZ * HD);
    zero_kernel<<<1024, 256>>>(h2, B_SZ * HD);
    zero_kernel<<<512, 256>>>(mulv, B_SZ * 200);
    conv_f16hi<<<4096, 256>>>(x_en, xEh, B_SZ, NV_EN, KP_EN);
    cudaStreamWaitEvent(0, eW1E, 0);
    launch_tch<0>(xEh, W1Eh, W1Eh, h1, B_SZ, HD, KP_EN, 16, 1, 0);
    bias_sp_conv<<<1024, 256>>>(h1, b1_en, Ahs, Alo, B_SZ, HD);
    cudaStreamWaitEvent(0, eWsmE, 0);
    launch_tc3<1>(Ahs, Alo, W2Ehi, W2Elo, h2, B_SZ, HD, 512, 8, 1, 0);
    bias_sp_conv<<<1024, 256>>>(h2, b2_en, Ahs, Alo, B_SZ, HD);
    launch_tc3<1>(Ahs, Alo, MVEhi, MVElo, mulv, B_SZ, 200, 512, 8, 1, 0);
    theta_kl_kernel<<<B_SZ, 128>>>(mulv, bmu_en, blv_en, eps_en, th_en, theta_en_out, thEhi, thElo, acc + 1);
    cudaEventRecord(eMt, 0);

    // ======== stream s1: CN encoder ========
    zero_kernel<<<1024, 256, 0, s1>>>(h1c, B_SZ * HD);
    zero_kernel<<<1024, 256, 0, s1>>>(h2c, B_SZ * HD);
    zero_kernel<<<512, 256, 0, s1>>>(mulvc, B_SZ * 200);
    conv_f16hi<<<4096, 256, 0, s1>>>(x_cn, xCh, B_SZ, NV_CN, KP_CN);
    cudaStreamWaitEvent(s1, eW1C, 0);
    launch_tch<0>(xCh, W1Ch, W1Ch, h1c, B_SZ, HD, KP_CN, 16, 1, s1);
    bias_sp_conv<<<1024, 256, 0, s1>>>(h1c, b1_cn, A2hs, A2lo, B_SZ, HD);
    cudaStreamWaitEvent(s1, eWsmC, 0);
    launch_tc3<1>(A2hs, A2lo, W2Chi, W2Clo, h2c, B_SZ, HD, 512, 8, 1, s1);
    bias_sp_conv<<<1024, 256, 0, s1>>>(h2c, b2_cn, A2hs, A2lo, B_SZ, HD);
    launch_tc3<1>(A2hs, A2lo, MVChi, MVClo, mulvc, B_SZ, 200, 512, 8, 1, s1);
    theta_kl_kernel<<<B_SZ, 128, 0, s1>>>(mulvc, bmu_cn, blv_cn, eps_cn, th_cn, theta_cn_out, thChi, thClo, acc + 3);
    cudaEventRecord(e1t, s1);

    // ======== recon tails (fused GEMM+loss) ========
    cudaStreamWaitEvent(s2, eMt, 0);
    launch_recon(thEhi, BEhi, x_en, rlE, B_SZ, NV_EN, 128, s2);
    recon_final<<<1, 512, 0, s2>>>(rlE, acc + 0);
    cudaEventRecord(e2e, s2);

    cudaStreamWaitEvent(s3, e1t, 0);
    launch_recon(thChi, BChi, x_cn, rlC, B_SZ, NV_CN, 128, s3);
    recon_final<<<1, 512, 0, s3>>>(rlC, acc + 2);
    cudaEventRecord(e3e, s3);

    // ======== stream 0: alignment, contrastive, join ========
    norm_topic_kernel<<<KT, 128>>>(topic, tnT);
    cmat_kernel<<<KT, 128>>>(tnT, Cm);
    sinkhorn_kernel<<<1, 256>>>(Cm, acc);
    cudaStreamWaitEvent(0, e1t, 0);
    select_norm_kernel<<<B_SZ, 128>>>(th_en, th_cn, tnb);
    contrast_kernel<<<B_SZ, 256>>>(tnb, cid, acc);
    cudaStreamWaitEvent(0, e2e, 0);
    cudaStreamWaitEvent(0, e3e, 0);
    finalize_kernel<<<1, 1>>>(acc, out);
}